// round 2
// baseline (speedup 1.0000x reference)
#include <cuda_runtime.h>
#include <cuda_bf16.h>
#include <math.h>

#define B_  4
#define L_  4096
#define HID_ 1024
#define NH_ 8
#define DH_ 128
#define HALF_ 64
#define ROWS_ (B_ * L_)          // 16384
#define SCALE_ 0.08838834764831845f  // 1/sqrt(128)

// ---------------- scratch (static device globals: allocation-free) ----------
__device__ float g_h[(size_t)ROWS_ * HID_];
__device__ float g_q[(size_t)ROWS_ * HID_];
__device__ float g_k[(size_t)ROWS_ * HID_];
__device__ float g_v[(size_t)ROWS_ * HID_];
__device__ float g_y[(size_t)ROWS_ * HID_];
__device__ float g_gates[3 * B_ * NH_ * L_];
__device__ float g_rope[2 * L_ * HALF_];

// ---------------- RMSNorm -----------------------------------------------
__global__ __launch_bounds__(256) void rmsnorm_kernel(
    const float* __restrict__ x, const float* __restrict__ w, float* __restrict__ h)
{
    int row = blockIdx.x;
    int tid = threadIdx.x;
    const float4* xr = (const float4*)(x + (size_t)row * HID_);
    float4 xv = xr[tid];
    float ss = xv.x * xv.x + xv.y * xv.y + xv.z * xv.z + xv.w * xv.w;
    #pragma unroll
    for (int off = 16; off; off >>= 1) ss += __shfl_xor_sync(0xFFFFFFFFu, ss, off);
    __shared__ float red[8];
    __shared__ float rtot;
    int lane = tid & 31, warp = tid >> 5;
    if (lane == 0) red[warp] = ss;
    __syncthreads();
    if (tid == 0) {
        float s = 0.f;
        #pragma unroll
        for (int i = 0; i < 8; i++) s += red[i];
        rtot = rsqrtf(s * (1.0f / HID_) + 1e-6f);
    }
    __syncthreads();
    float r = rtot;
    const float4* wr = (const float4*)w;
    float4 wv = wr[tid];
    float4 o;
    o.x = xv.x * r * wv.x; o.y = xv.y * r * wv.y;
    o.z = xv.z * r * wv.z; o.w = xv.w * r * wv.w;
    ((float4*)(h + (size_t)row * HID_))[tid] = o;
}

// ---------------- SGEMM: C[M,N] = A[M,K] * W[N,K]^T (+bias) ---------------
#define GBM 128
#define GBN 128
#define GBK 8
__global__ __launch_bounds__(256) void sgemm_nt(
    const float* __restrict__ A, const float* __restrict__ W,
    const float* __restrict__ bias, float* __restrict__ C,
    int M, int N, int K)
{
    __shared__ float As[GBK][GBM];
    __shared__ float Bs[GBK][GBN];
    int tid = threadIdx.x;
    int bm = blockIdx.y, bn = blockIdx.x;
    int lrow = tid >> 1;
    int lcol = (tid & 1) * 4;
    int trow = (tid >> 4) * 8;
    int tcol = (tid & 15) * 8;
    const float* Ap = A + (size_t)(bm * GBM + lrow) * K + lcol;
    const float* Bp = W + (size_t)(bn * GBN + lrow) * K + lcol;

    float acc[8][8];
    #pragma unroll
    for (int i = 0; i < 8; i++)
        #pragma unroll
        for (int j = 0; j < 8; j++) acc[i][j] = 0.f;

    for (int k0 = 0; k0 < K; k0 += GBK) {
        float4 a = *(const float4*)(Ap + k0);
        float4 b = *(const float4*)(Bp + k0);
        __syncthreads();
        As[lcol + 0][lrow] = a.x; As[lcol + 1][lrow] = a.y;
        As[lcol + 2][lrow] = a.z; As[lcol + 3][lrow] = a.w;
        Bs[lcol + 0][lrow] = b.x; Bs[lcol + 1][lrow] = b.y;
        Bs[lcol + 2][lrow] = b.z; Bs[lcol + 3][lrow] = b.w;
        __syncthreads();
        #pragma unroll
        for (int kk = 0; kk < GBK; kk++) {
            float ra[8], rb[8];
            #pragma unroll
            for (int i = 0; i < 8; i++) ra[i] = As[kk][trow + i];
            #pragma unroll
            for (int j = 0; j < 8; j++) rb[j] = Bs[kk][tcol + j];
            #pragma unroll
            for (int i = 0; i < 8; i++)
                #pragma unroll
                for (int j = 0; j < 8; j++) acc[i][j] += ra[i] * rb[j];
        }
    }

    #pragma unroll
    for (int j = 0; j < 8; j++) {
        float bv = bias ? bias[bn * GBN + tcol + j] : 0.f;
        #pragma unroll
        for (int i = 0; i < 8; i++) {
            size_t ci = (size_t)(bm * GBM + trow + i) * N + bn * GBN + tcol + j;
            C[ci] = acc[i][j] + bv;
        }
    }
}

// ---------------- Gates: sigmoid(h . W[h] + b) per (row, head) ------------
__global__ __launch_bounds__(256) void gates_kernel(
    const float* __restrict__ h,
    const float* __restrict__ Wb, const float* __restrict__ bb,
    const float* __restrict__ Wi, const float* __restrict__ bi,
    const float* __restrict__ Wo, const float* __restrict__ bo,
    float* __restrict__ gates)
{
    int row = blockIdx.x;              // b*L + t
    int tid = threadIdx.x;
    __shared__ float hs[HID_];
    const float* hr = h + (size_t)row * HID_;
    for (int i = tid; i < HID_; i += 256) hs[i] = hr[i];
    __syncthreads();
    int w = tid >> 5, lane = tid & 31;   // warp = head
    int b = row / L_, t = row % L_;
    const float* Ws[3] = {Wb, Wi, Wo};
    const float* bs[3] = {bb, bi, bo};
    #pragma unroll
    for (int gt = 0; gt < 3; gt++) {
        const float* wrow = Ws[gt] + w * HID_;
        float sum = 0.f;
        for (int i = lane; i < HID_; i += 32) sum += hs[i] * wrow[i];
        #pragma unroll
        for (int off = 16; off; off >>= 1) sum += __shfl_xor_sync(0xFFFFFFFFu, sum, off);
        if (lane == 0) {
            float val = 1.f / (1.f + expf(-(sum + bs[gt][w])));
            gates[(size_t)gt * (B_ * NH_ * L_) + (size_t)(b * NH_ + w) * L_ + t] = val;
        }
    }
}

// ---------------- RoPE tables (double-precision trig for large angles) ----
__global__ void rope_table_kernel(float* __restrict__ tab)
{
    int idx = blockIdx.x * blockDim.x + threadIdx.x;
    if (idx >= L_ * HALF_) return;
    int t = idx >> 6, j = idx & 63;
    double invf = exp(-(double)j / 64.0 * 9.210340371976182736);  // ln(10000)
    float ang = (float)t * (float)invf;
    tab[idx] = (float)cos((double)ang);
    tab[L_ * HALF_ + idx] = (float)sin((double)ang);
}

// ---------------- RoPE apply (in-place on q and k) ------------------------
__global__ __launch_bounds__(512) void rope_apply_kernel(
    float* __restrict__ q, float* __restrict__ k, const float* __restrict__ tab)
{
    int row = blockIdx.x;
    int t = row % L_;
    int tid = threadIdx.x;
    int hh = tid >> 6, j = tid & 63;
    size_t base = (size_t)row * HID_ + hh * DH_;
    float c = tab[t * HALF_ + j];
    float s = tab[L_ * HALF_ + t * HALF_ + j];
    float q1 = q[base + j], q2 = q[base + HALF_ + j];
    q[base + j]          = q1 * c - q2 * s;
    q[base + HALF_ + j]  = q1 * s + q2 * c;
    float k1 = k[base + j], k2 = k[base + HALF_ + j];
    k[base + j]          = k1 * c - k2 * s;
    k[base + HALF_ + j]  = k1 * s + k2 * c;
}

// ---------------- Recurrence: thread e owns full column M[:,e] ------------
__global__ __launch_bounds__(128, 1) void recurrence_kernel(
    const float* __restrict__ q, const float* __restrict__ k,
    const float* __restrict__ v, const float* __restrict__ gates,
    float* __restrict__ y)
{
    int bh = blockIdx.x;          // b*NH + h
    int b = bh >> 3, hh = bh & 7;
    int e = threadIdx.x;

    const float* fp = gates + (size_t)bh * L_;
    const float* gp = gates + (size_t)(B_ * NH_ + bh) * L_;
    const float* op = gates + (size_t)(2 * B_ * NH_ + bh) * L_;

    __shared__ float qs[DH_], ks[DH_];
    float M[DH_];
    #pragma unroll
    for (int d = 0; d < DH_; d++) M[d] = 0.f;

    size_t base0 = (size_t)b * L_ * HID_ + hh * DH_ + e;

    // prefetch t = 0
    float qn = q[base0], kn = k[base0], vn = v[base0];
    float fn = fp[0], gn = gp[0], on = op[0];

    for (int t = 0; t < L_; t++) {
        __syncthreads();               // previous step finished reading qs/ks
        qs[e] = qn; ks[e] = kn;
        float ff = fn, oo = on;
        float c1 = gn * SCALE_ * vn;
        __syncthreads();               // qs/ks visible
        if (t + 1 < L_) {              // prefetch next step (overlaps compute)
            size_t bn = base0 + (size_t)(t + 1) * HID_;
            qn = q[bn]; kn = k[bn]; vn = v[bn];
            fn = fp[t + 1]; gn = gp[t + 1]; on = op[t + 1];
        }
        float a0 = 0.f, a1 = 0.f, a2 = 0.f, a3 = 0.f;
        #pragma unroll
        for (int d = 0; d < DH_; d += 4) {
            M[d]     = M[d]     * ff + c1 * ks[d];     a0 += qs[d]     * M[d];
            M[d + 1] = M[d + 1] * ff + c1 * ks[d + 1]; a1 += qs[d + 1] * M[d + 1];
            M[d + 2] = M[d + 2] * ff + c1 * ks[d + 2]; a2 += qs[d + 2] * M[d + 2];
            M[d + 3] = M[d + 3] * ff + c1 * ks[d + 3]; a3 += qs[d + 3] * M[d + 3];
        }
        y[base0 + (size_t)t * HID_] = oo * ((a0 + a1) + (a2 + a3));
    }
}

// ---------------- launch ---------------------------------------------------
extern "C" void kernel_launch(void* const* d_in, const int* in_sizes, int n_in,
                              void* d_out, int out_size)
{
    const float* x      = (const float*)d_in[0];
    const float* norm_w = (const float*)d_in[1];
    const float* Wq     = (const float*)d_in[2];
    const float* Wk     = (const float*)d_in[3];
    const float* Wv     = (const float*)d_in[4];
    const float* Wbeta  = (const float*)d_in[5];
    const float* bbeta  = (const float*)d_in[6];
    const float* Wig    = (const float*)d_in[7];
    const float* big    = (const float*)d_in[8];
    const float* Wog    = (const float*)d_in[9];
    const float* bog    = (const float*)d_in[10];
    const float* Wout   = (const float*)d_in[11];
    const float* bout   = (const float*)d_in[12];
    float* out = (float*)d_out;

    float *hbuf, *qb, *kb, *vb, *yb, *gb, *rt;
    cudaGetSymbolAddress((void**)&hbuf, g_h);
    cudaGetSymbolAddress((void**)&qb,   g_q);
    cudaGetSymbolAddress((void**)&kb,   g_k);
    cudaGetSymbolAddress((void**)&vb,   g_v);
    cudaGetSymbolAddress((void**)&yb,   g_y);
    cudaGetSymbolAddress((void**)&gb,   g_gates);
    cudaGetSymbolAddress((void**)&rt,   g_rope);

    rmsnorm_kernel<<<ROWS_, 256>>>(x, norm_w, hbuf);

    dim3 ggrid(HID_ / GBN, ROWS_ / GBM);
    sgemm_nt<<<ggrid, 256>>>(hbuf, Wq, nullptr, qb, ROWS_, HID_, HID_);
    sgemm_nt<<<ggrid, 256>>>(hbuf, Wk, nullptr, kb, ROWS_, HID_, HID_);
    sgemm_nt<<<ggrid, 256>>>(hbuf, Wv, nullptr, vb, ROWS_, HID_, HID_);

    gates_kernel<<<ROWS_, 256>>>(hbuf, Wbeta, bbeta, Wig, big, Wog, bog, gb);

    rope_table_kernel<<<(L_ * HALF_ + 255) / 256, 256>>>(rt);
    rope_apply_kernel<<<ROWS_, 512>>>(qb, kb, rt);

    recurrence_kernel<<<B_ * NH_, 128>>>(qb, kb, vb, gb, yb);

    sgemm_nt<<<ggrid, 256>>>(yb, Wout, bout, out, ROWS_, HID_, HID_);
}

// round 3
// speedup vs baseline: 1.8786x; 1.8786x over previous
#include <cuda_runtime.h>
#include <cuda_bf16.h>
#include <math.h>
#include <stdint.h>

#define B_  4
#define L_  4096
#define HID_ 1024
#define NH_ 8
#define DH_ 128
#define HALF_ 64
#define ROWS_ (B_ * L_)          // 16384
#define SCALE_ 0.08838834764831845f  // 1/sqrt(128)

// ---------------- scratch (static device globals: allocation-free) ----------
__device__ float g_h[(size_t)ROWS_ * HID_];
__device__ __nv_bfloat16 g_hh[(size_t)ROWS_ * HID_];
__device__ __nv_bfloat16 g_hl[(size_t)ROWS_ * HID_];
__device__ float g_q[(size_t)ROWS_ * HID_];
__device__ float g_k[(size_t)ROWS_ * HID_];
__device__ float g_v[(size_t)ROWS_ * HID_];
__device__ __nv_bfloat16 g_yh[(size_t)ROWS_ * HID_];
__device__ __nv_bfloat16 g_yl[(size_t)ROWS_ * HID_];
__device__ __nv_bfloat16 g_wh[(size_t)4 * HID_ * HID_];
__device__ __nv_bfloat16 g_wl[(size_t)4 * HID_ * HID_];
__device__ float g_gates[3 * B_ * NH_ * L_];
__device__ float g_rope[2 * L_ * HALF_];

// ---------------- helpers -------------------------------------------------
__device__ __forceinline__ uint32_t s2u(const void* p) {
    return (uint32_t)__cvta_generic_to_shared(p);
}
__device__ __forceinline__ void cp16(uint32_t d, const void* p) {
    asm volatile("cp.async.cg.shared.global [%0],[%1],16;" :: "r"(d), "l"(p));
}
__device__ __forceinline__ void cp4(uint32_t d, const void* p) {
    asm volatile("cp.async.ca.shared.global [%0],[%1],4;" :: "r"(d), "l"(p));
}
__device__ __forceinline__ void cp_commit() {
    asm volatile("cp.async.commit_group;");
}
__device__ __forceinline__ void ldsm4(uint32_t* r, uint32_t a) {
    asm volatile("ldmatrix.sync.aligned.m8n8.x4.shared.b16 {%0,%1,%2,%3},[%4];"
                 : "=r"(r[0]), "=r"(r[1]), "=r"(r[2]), "=r"(r[3]) : "r"(a));
}
__device__ __forceinline__ void mma16816(float* c, const uint32_t* a, const uint32_t* b) {
    asm volatile("mma.sync.aligned.m16n8k16.row.col.f32.bf16.bf16.f32 "
                 "{%0,%1,%2,%3},{%4,%5,%6,%7},{%8,%9},{%0,%1,%2,%3};"
                 : "+f"(c[0]), "+f"(c[1]), "+f"(c[2]), "+f"(c[3])
                 : "r"(a[0]), "r"(a[1]), "r"(a[2]), "r"(a[3]), "r"(b[0]), "r"(b[1]));
}
__device__ __forceinline__ unsigned long long pk2(float a, float b) {
    unsigned long long r;
    asm("mov.b64 %0,{%1,%2};" : "=l"(r) : "r"(__float_as_uint(a)), "r"(__float_as_uint(b)));
    return r;
}
__device__ __forceinline__ unsigned long long mulx2(unsigned long long a, unsigned long long b) {
    unsigned long long r;
    asm("mul.rn.f32x2 %0,%1,%2;" : "=l"(r) : "l"(a), "l"(b));
    return r;
}
__device__ __forceinline__ unsigned long long fmax2(unsigned long long a, unsigned long long b, unsigned long long c) {
    unsigned long long r;
    asm("fma.rn.f32x2 %0,%1,%2,%3;" : "=l"(r) : "l"(a), "l"(b), "l"(c));
    return r;
}
__device__ __forceinline__ float upksum(unsigned long long v) {
    uint32_t lo, hi;
    asm("mov.b64 {%0,%1},%2;" : "=r"(lo), "=r"(hi) : "l"(v));
    return __uint_as_float(lo) + __uint_as_float(hi);
}
__device__ __forceinline__ void ldsv2(unsigned long long& a, unsigned long long& b, uint32_t addr) {
    asm volatile("ld.shared.v2.u64 {%0,%1},[%2];" : "=l"(a), "=l"(b) : "r"(addr));
}

// ---------------- RMSNorm (also emits bf16 hi/lo split) -------------------
__global__ __launch_bounds__(256) void rmsnorm_kernel(
    const float* __restrict__ x, const float* __restrict__ w, float* __restrict__ h,
    __nv_bfloat16* __restrict__ hh, __nv_bfloat16* __restrict__ hl)
{
    int row = blockIdx.x;
    int tid = threadIdx.x;
    const float4* xr = (const float4*)(x + (size_t)row * HID_);
    float4 xv = xr[tid];
    float ss = xv.x * xv.x + xv.y * xv.y + xv.z * xv.z + xv.w * xv.w;
    #pragma unroll
    for (int off = 16; off; off >>= 1) ss += __shfl_xor_sync(0xFFFFFFFFu, ss, off);
    __shared__ float red[8];
    __shared__ float rtot;
    int lane = tid & 31, warp = tid >> 5;
    if (lane == 0) red[warp] = ss;
    __syncthreads();
    if (tid == 0) {
        float s = 0.f;
        #pragma unroll
        for (int i = 0; i < 8; i++) s += red[i];
        rtot = rsqrtf(s * (1.0f / HID_) + 1e-6f);
    }
    __syncthreads();
    float r = rtot;
    const float4* wr = (const float4*)w;
    float4 wv = wr[tid];
    float o[4];
    o[0] = xv.x * r * wv.x; o[1] = xv.y * r * wv.y;
    o[2] = xv.z * r * wv.z; o[3] = xv.w * r * wv.w;
    ((float4*)(h + (size_t)row * HID_))[tid] = *(float4*)o;
    __nv_bfloat16 hi[4], lo[4];
    #pragma unroll
    for (int i = 0; i < 4; i++) {
        hi[i] = __float2bfloat16(o[i]);
        lo[i] = __float2bfloat16(o[i] - __bfloat162float(hi[i]));
    }
    size_t base = (size_t)row * HID_;
    ((__nv_bfloat162*)(hh + base))[tid * 2]     = __halves2bfloat162(hi[0], hi[1]);
    ((__nv_bfloat162*)(hh + base))[tid * 2 + 1] = __halves2bfloat162(hi[2], hi[3]);
    ((__nv_bfloat162*)(hl + base))[tid * 2]     = __halves2bfloat162(lo[0], lo[1]);
    ((__nv_bfloat162*)(hl + base))[tid * 2 + 1] = __halves2bfloat162(lo[2], lo[3]);
}

// ---------------- fp32 -> bf16 hi/lo split (weights) -----------------------
__global__ __launch_bounds__(256) void splitf_kernel(
    const float* __restrict__ s, __nv_bfloat16* __restrict__ hi,
    __nv_bfloat16* __restrict__ lo, int n4)
{
    int i = blockIdx.x * blockDim.x + threadIdx.x;
    if (i >= n4) return;
    float4 x = ((const float4*)s)[i];
    float v[4] = {x.x, x.y, x.z, x.w};
    __nv_bfloat16 h[4], l[4];
    #pragma unroll
    for (int j = 0; j < 4; j++) {
        h[j] = __float2bfloat16(v[j]);
        l[j] = __float2bfloat16(v[j] - __bfloat162float(h[j]));
    }
    ((__nv_bfloat162*)hi)[i * 2]     = __halves2bfloat162(h[0], h[1]);
    ((__nv_bfloat162*)hi)[i * 2 + 1] = __halves2bfloat162(h[2], h[3]);
    ((__nv_bfloat162*)lo)[i * 2]     = __halves2bfloat162(l[0], l[1]);
    ((__nv_bfloat162*)lo)[i * 2 + 1] = __halves2bfloat162(l[2], l[3]);
}

// ---------------- bf16-split GEMM: C = A * W^T (+bias), fp32 out ----------
// A: [M,K] hi/lo bf16, W: [N,K] hi/lo bf16 (k contiguous), C: [M,N] fp32.
// Block 128x128xBK32, 8 warps (4x2), warp tile 32x64, m16n8k16 mma,
// 3-product compensation: Ah*Bh + Ah*Bl + Al*Bh.
#define GTILE 5120          // 128 * 40 bf16 elems per tile
#define GSTAGEB (4 * GTILE * 2)  // bytes per stage (Ah,Al,Bh,Bl)
#define GSMEM (2 * GSTAGEB)      // 81920 bytes

__global__ __launch_bounds__(256) void gemm_bf16x2(
    const __nv_bfloat16* __restrict__ Ah, const __nv_bfloat16* __restrict__ Al,
    const __nv_bfloat16* __restrict__ Bh, const __nv_bfloat16* __restrict__ Bl,
    const float* __restrict__ bias, float* __restrict__ C,
    int M, int N, int K)
{
    extern __shared__ __nv_bfloat16 sm[];
    uint32_t sbase = s2u(sm);
    int tid = threadIdx.x;
    int bm = blockIdx.y, bn = blockIdx.x;
    int w = tid >> 5, lane = tid & 31;
    int wm = (w & 3) * 32, wn = (w >> 2) * 64;
    int g = lane >> 2, tq = lane & 3;

    const __nv_bfloat16* srcs[4];
    srcs[0] = Ah + (size_t)(bm * 128) * K;
    srcs[1] = Al + (size_t)(bm * 128) * K;
    srcs[2] = Bh + (size_t)(bn * 128) * K;
    srcs[3] = Bl + (size_t)(bn * 128) * K;

    float acc[2][8][4];
    #pragma unroll
    for (int i = 0; i < 2; i++)
        #pragma unroll
        for (int j = 0; j < 8; j++)
            #pragma unroll
            for (int q = 0; q < 4; q++) acc[i][j][q] = 0.f;

    // ldmatrix per-lane offsets
    int rA = (lane & 7) + ((lane & 8) ? 8 : 0);
    int cA = (lane & 16) ? 8 : 0;
    int rB = (lane & 7) + ((lane & 16) ? 8 : 0);
    int cB = (lane & 8) ? 8 : 0;

    auto loadStage = [&](int st, int k0) {
        #pragma unroll
        for (int mtx = 0; mtx < 4; mtx++) {
            uint32_t dbase = sbase + st * GSTAGEB + mtx * (GTILE * 2);
            const __nv_bfloat16* s = srcs[mtx] + k0;
            #pragma unroll
            for (int rep = 0; rep < 2; rep++) {
                int j = tid + rep * 256;
                int row = j >> 2, cc = j & 3;
                cp16(dbase + row * 80 + cc * 16, s + (size_t)row * K + cc * 8);
            }
        }
    };

    loadStage(0, 0);
    cp_commit();
    asm volatile("cp.async.wait_group 0;");
    __syncthreads();

    int niter = K / 32;
    for (int it = 0; it < niter; it++) {
        int cur = it & 1;
        if (it + 1 < niter) {
            loadStage(cur ^ 1, (it + 1) * 32);
        }
        cp_commit();
        uint32_t stb = sbase + cur * GSTAGEB;
        #pragma unroll
        for (int ks = 0; ks < 2; ks++) {
            int kb = ks * 16;
            uint32_t a_h[2][4], a_l[2][4];
            #pragma unroll
            for (int mi = 0; mi < 2; mi++) {
                uint32_t ad = stb + ((wm + mi * 16 + rA) * 40 + kb + cA) * 2;
                ldsm4(a_h[mi], ad);
                ldsm4(a_l[mi], ad + GTILE * 2);
            }
            #pragma unroll
            for (int np = 0; np < 4; np++) {
                uint32_t bd = stb + 2 * GTILE * 2 + ((wn + np * 16 + rB) * 40 + kb + cB) * 2;
                uint32_t b_h[4], b_l[4];
                ldsm4(b_h, bd);
                ldsm4(b_l, bd + GTILE * 2);
                #pragma unroll
                for (int mi = 0; mi < 2; mi++) {
                    mma16816(acc[mi][np * 2],     a_h[mi], b_h);
                    mma16816(acc[mi][np * 2 + 1], a_h[mi], b_h + 2);
                    mma16816(acc[mi][np * 2],     a_h[mi], b_l);
                    mma16816(acc[mi][np * 2 + 1], a_h[mi], b_l + 2);
                    mma16816(acc[mi][np * 2],     a_l[mi], b_h);
                    mma16816(acc[mi][np * 2 + 1], a_l[mi], b_h + 2);
                }
            }
        }
        asm volatile("cp.async.wait_group 0;");
        __syncthreads();
    }

    int rowb = bm * 128 + wm;
    int colb = bn * 128 + wn;
    #pragma unroll
    for (int mi = 0; mi < 2; mi++) {
        int r0 = rowb + mi * 16 + g;
        #pragma unroll
        for (int nj = 0; nj < 8; nj++) {
            int cc = colb + nj * 8 + tq * 2;
            float bx = 0.f, by = 0.f;
            if (bias) { float2 b2 = *(const float2*)(bias + cc); bx = b2.x; by = b2.y; }
            float2 o0, o1;
            o0.x = acc[mi][nj][0] + bx; o0.y = acc[mi][nj][1] + by;
            o1.x = acc[mi][nj][2] + bx; o1.y = acc[mi][nj][3] + by;
            *(float2*)(C + (size_t)r0 * N + cc) = o0;
            *(float2*)(C + (size_t)(r0 + 8) * N + cc) = o1;
        }
    }
}

// ---------------- Gates: sigmoid(h . W[h] + b) per (row, head) ------------
__global__ __launch_bounds__(256) void gates_kernel(
    const float* __restrict__ h,
    const float* __restrict__ Wb, const float* __restrict__ bb,
    const float* __restrict__ Wi, const float* __restrict__ bi,
    const float* __restrict__ Wo, const float* __restrict__ bo,
    float* __restrict__ gates)
{
    int row = blockIdx.x;
    int tid = threadIdx.x;
    __shared__ float hs[HID_];
    const float* hr = h + (size_t)row * HID_;
    for (int i = tid; i < HID_; i += 256) hs[i] = hr[i];
    __syncthreads();
    int w = tid >> 5, lane = tid & 31;
    int b = row / L_, t = row % L_;
    const float* Ws[3] = {Wb, Wi, Wo};
    const float* bs[3] = {bb, bi, bo};
    #pragma unroll
    for (int gt = 0; gt < 3; gt++) {
        const float* wrow = Ws[gt] + w * HID_;
        float sum = 0.f;
        for (int i = lane; i < HID_; i += 32) sum += hs[i] * wrow[i];
        #pragma unroll
        for (int off = 16; off; off >>= 1) sum += __shfl_xor_sync(0xFFFFFFFFu, sum, off);
        if (lane == 0) {
            float val = 1.f / (1.f + expf(-(sum + bs[gt][w])));
            gates[(size_t)gt * (B_ * NH_ * L_) + (size_t)(b * NH_ + w) * L_ + t] = val;
        }
    }
}

// ---------------- RoPE tables ---------------------------------------------
__global__ void rope_table_kernel(float* __restrict__ tab)
{
    int idx = blockIdx.x * blockDim.x + threadIdx.x;
    if (idx >= L_ * HALF_) return;
    int t = idx >> 6, j = idx & 63;
    double invf = exp(-(double)j / 64.0 * 9.210340371976182736);
    float ang = (float)t * (float)invf;
    tab[idx] = (float)cos((double)ang);
    tab[L_ * HALF_ + idx] = (float)sin((double)ang);
}

// ---------------- RoPE apply ----------------------------------------------
__global__ __launch_bounds__(512) void rope_apply_kernel(
    float* __restrict__ q, float* __restrict__ k, const float* __restrict__ tab)
{
    int row = blockIdx.x;
    int t = row % L_;
    int tid = threadIdx.x;
    int hh = tid >> 6, j = tid & 63;
    size_t base = (size_t)row * HID_ + hh * DH_;
    float c = tab[t * HALF_ + j];
    float s = tab[L_ * HALF_ + t * HALF_ + j];
    float q1 = q[base + j], q2 = q[base + HALF_ + j];
    q[base + j]          = q1 * c - q2 * s;
    q[base + HALF_ + j]  = q1 * s + q2 * c;
    float k1 = k[base + j], k2 = k[base + HALF_ + j];
    k[base + j]          = k1 * c - k2 * s;
    k[base + HALF_ + j]  = k1 * s + k2 * c;
}

// ---------------- Recurrence: 8 blocks per (b,h), 16 cols each -------------
// thread (c, rg): owns M[rg*16 .. rg*16+15][col0+c]; 128 threads = 16c x 8rg.
#define NSTG 8
#define STGF 340       // floats per stage: q 8x20, k 8x20, v 16, fgo 4
__global__ __launch_bounds__(128) void recurrence2_kernel(
    const float* __restrict__ q, const float* __restrict__ k,
    const float* __restrict__ v, const float* __restrict__ gates,
    __nv_bfloat16* __restrict__ yh, __nv_bfloat16* __restrict__ yl)
{
    __shared__ float rs[NSTG * STGF];
    int split = blockIdx.x, bh = blockIdx.y;
    int b = bh >> 3, hh = bh & 7;
    int tid = threadIdx.x;
    int c = tid >> 3, rg = tid & 7;
    int col0 = split * 16;
    size_t headbase = (size_t)b * L_ * HID_ + hh * DH_;
    const float* fp = gates + (size_t)bh * L_;
    const float* gp = fp + (size_t)(B_ * NH_) * L_;
    const float* op = gp + (size_t)(B_ * NH_) * L_;
    uint32_t sb = s2u(rs);

    auto issue = [&](int t) {
        if (t >= L_) return;
        uint32_t base = sb + (t & (NSTG - 1)) * (STGF * 4);
        size_t row = headbase + (size_t)t * HID_;
        if (tid < 32) {
            cp16(base + (tid >> 2) * 80 + (tid & 3) * 16, q + row + tid * 4);
        } else if (tid < 64) {
            int j = tid - 32;
            cp16(base + 640 + (j >> 2) * 80 + (j & 3) * 16, k + row + j * 4);
        } else if (tid < 68) {
            int j = tid - 64;
            cp16(base + 1280 + j * 16, v + row + col0 + j * 4);
        } else if (tid < 71) {
            int j = tid - 68;
            const float* p = (j == 0 ? fp : (j == 1 ? gp : op)) + t;
            cp4(base + 1344 + j * 4, p);
        }
    };

    // prologue: prefetch 7 steps
    for (int t = 0; t < 7; t++) { issue(t); cp_commit(); }

    unsigned long long M2[8];
    #pragma unroll
    for (int i = 0; i < 8; i++) M2[i] = 0ull;

    for (int t = 0; t < L_; t++) {
        int st = t & (NSTG - 1);
        asm volatile("cp.async.wait_group 6;");
        __syncthreads();
        float ff = rs[st * STGF + 336];
        float gg = rs[st * STGF + 337];
        float oo = rs[st * STGF + 338];
        float vv = rs[st * STGF + 320 + c];
        float c1 = gg * SCALE_ * vv;
        unsigned long long ffp = pk2(ff, ff);
        unsigned long long c1p = pk2(c1, c1);
        unsigned long long p2 = 0ull;
        uint32_t qa = sb + st * (STGF * 4) + rg * 80;
        uint32_t ka = qa + 640;
        #pragma unroll
        for (int i = 0; i < 4; i++) {
            unsigned long long k0, k1, q0, q1, t0;
            ldsv2(k0, k1, ka + i * 16);
            ldsv2(q0, q1, qa + i * 16);
            t0 = mulx2(c1p, k0);
            M2[2 * i] = fmax2(M2[2 * i], ffp, t0);
            p2 = fmax2(q0, M2[2 * i], p2);
            t0 = mulx2(c1p, k1);
            M2[2 * i + 1] = fmax2(M2[2 * i + 1], ffp, t0);
            p2 = fmax2(q1, M2[2 * i + 1], p2);
        }
        float p = upksum(p2);
        p += __shfl_xor_sync(0xFFFFFFFFu, p, 1);
        p += __shfl_xor_sync(0xFFFFFFFFu, p, 2);
        p += __shfl_xor_sync(0xFFFFFFFFu, p, 4);
        if (rg == 0) {
            float yv = oo * p;
            size_t yi = headbase + (size_t)t * HID_ + col0 + c;
            __nv_bfloat16 h16 = __float2bfloat16(yv);
            yh[yi] = h16;
            yl[yi] = __float2bfloat16(yv - __bfloat162float(h16));
        }
        issue(t + 7);
        cp_commit();
    }
}

// ---------------- launch ---------------------------------------------------
extern "C" void kernel_launch(void* const* d_in, const int* in_sizes, int n_in,
                              void* d_out, int out_size)
{
    const float* x      = (const float*)d_in[0];
    const float* norm_w = (const float*)d_in[1];
    const float* Wq     = (const float*)d_in[2];
    const float* Wk     = (const float*)d_in[3];
    const float* Wv     = (const float*)d_in[4];
    const float* Wbeta  = (const float*)d_in[5];
    const float* bbeta  = (const float*)d_in[6];
    const float* Wig    = (const float*)d_in[7];
    const float* big    = (const float*)d_in[8];
    const float* Wog    = (const float*)d_in[9];
    const float* bog    = (const float*)d_in[10];
    const float* Wout   = (const float*)d_in[11];
    const float* bout   = (const float*)d_in[12];
    float* out = (float*)d_out;

    float *hbuf, *qb, *kb, *vb, *gb, *rt;
    __nv_bfloat16 *hh, *hl, *yh, *yl, *wh, *wl;
    cudaGetSymbolAddress((void**)&hbuf, g_h);
    cudaGetSymbolAddress((void**)&hh,   g_hh);
    cudaGetSymbolAddress((void**)&hl,   g_hl);
    cudaGetSymbolAddress((void**)&qb,   g_q);
    cudaGetSymbolAddress((void**)&kb,   g_k);
    cudaGetSymbolAddress((void**)&vb,   g_v);
    cudaGetSymbolAddress((void**)&yh,   g_yh);
    cudaGetSymbolAddress((void**)&yl,   g_yl);
    cudaGetSymbolAddress((void**)&wh,   g_wh);
    cudaGetSymbolAddress((void**)&wl,   g_wl);
    cudaGetSymbolAddress((void**)&gb,   g_gates);
    cudaGetSymbolAddress((void**)&rt,   g_rope);

    cudaFuncSetAttribute(gemm_bf16x2, cudaFuncAttributeMaxDynamicSharedMemorySize, GSMEM);

    const size_t WSZ = (size_t)HID_ * HID_;
    const int n4 = (int)(WSZ / 4);

    rmsnorm_kernel<<<ROWS_, 256>>>(x, norm_w, hbuf, hh, hl);

    splitf_kernel<<<(n4 + 255) / 256, 256>>>(Wq,   wh,           wl,           n4);
    splitf_kernel<<<(n4 + 255) / 256, 256>>>(Wk,   wh + WSZ,     wl + WSZ,     n4);
    splitf_kernel<<<(n4 + 255) / 256, 256>>>(Wv,   wh + 2 * WSZ, wl + 2 * WSZ, n4);
    splitf_kernel<<<(n4 + 255) / 256, 256>>>(Wout, wh + 3 * WSZ, wl + 3 * WSZ, n4);

    dim3 ggrid(HID_ / 128, ROWS_ / 128);
    gemm_bf16x2<<<ggrid, 256, GSMEM>>>(hh, hl, wh,           wl,           nullptr, qb, ROWS_, HID_, HID_);
    gemm_bf16x2<<<ggrid, 256, GSMEM>>>(hh, hl, wh + WSZ,     wl + WSZ,     nullptr, kb, ROWS_, HID_, HID_);
    gemm_bf16x2<<<ggrid, 256, GSMEM>>>(hh, hl, wh + 2 * WSZ, wl + 2 * WSZ, nullptr, vb, ROWS_, HID_, HID_);

    gates_kernel<<<ROWS_, 256>>>(hbuf, Wbeta, bbeta, Wig, big, Wog, bog, gb);

    rope_table_kernel<<<(L_ * HALF_ + 255) / 256, 256>>>(rt);
    rope_apply_kernel<<<ROWS_, 512>>>(qb, kb, rt);

    recurrence2_kernel<<<dim3(8, B_ * NH_), 128>>>(qb, kb, vb, gb, yh, yl);

    gemm_bf16x2<<<ggrid, 256, GSMEM>>>(yh, yl, wh + 3 * WSZ, wl + 3 * WSZ, bout, out, ROWS_, HID_, HID_);
}

// round 5
// speedup vs baseline: 2.1972x; 1.1696x over previous
#include <cuda_runtime.h>
#include <cuda_bf16.h>
#include <math.h>
#include <stdint.h>

#define B_  4
#define L_  4096
#define HID_ 1024
#define NH_ 8
#define DH_ 128
#define HALF_ 64
#define ROWS_ (B_ * L_)          // 16384
#define SCALE_ 0.08838834764831845f  // 1/sqrt(128)

// ---------------- scratch (static device globals: allocation-free) ----------
__device__ float g_h[(size_t)ROWS_ * HID_];
__device__ __nv_bfloat16 g_hh[(size_t)ROWS_ * HID_];
__device__ __nv_bfloat16 g_hl[(size_t)ROWS_ * HID_];
__device__ float g_q[(size_t)ROWS_ * HID_];
__device__ float g_k[(size_t)ROWS_ * HID_];
__device__ float g_v[(size_t)ROWS_ * HID_];
__device__ __nv_bfloat16 g_yh[(size_t)ROWS_ * HID_];
__device__ __nv_bfloat16 g_yl[(size_t)ROWS_ * HID_];
__device__ __nv_bfloat16 g_wh[(size_t)4 * HID_ * HID_];
__device__ __nv_bfloat16 g_wl[(size_t)4 * HID_ * HID_];
__device__ float g_gates[3 * B_ * NH_ * L_];
__device__ float g_rope[2 * L_ * HALF_];

// ---------------- helpers -------------------------------------------------
__device__ __forceinline__ uint32_t s2u(const void* p) {
    return (uint32_t)__cvta_generic_to_shared(p);
}
__device__ __forceinline__ void cp16(uint32_t d, const void* p) {
    asm volatile("cp.async.cg.shared.global [%0],[%1],16;" :: "r"(d), "l"(p));
}
__device__ __forceinline__ void cp4(uint32_t d, const void* p) {
    asm volatile("cp.async.ca.shared.global [%0],[%1],4;" :: "r"(d), "l"(p));
}
__device__ __forceinline__ void cp_commit() {
    asm volatile("cp.async.commit_group;");
}
__device__ __forceinline__ void ldsm4(uint32_t* r, uint32_t a) {
    asm volatile("ldmatrix.sync.aligned.m8n8.x4.shared.b16 {%0,%1,%2,%3},[%4];"
                 : "=r"(r[0]), "=r"(r[1]), "=r"(r[2]), "=r"(r[3]) : "r"(a));
}
__device__ __forceinline__ void mma16816(float* c, const uint32_t* a, const uint32_t* b) {
    asm volatile("mma.sync.aligned.m16n8k16.row.col.f32.bf16.bf16.f32 "
                 "{%0,%1,%2,%3},{%4,%5,%6,%7},{%8,%9},{%0,%1,%2,%3};"
                 : "+f"(c[0]), "+f"(c[1]), "+f"(c[2]), "+f"(c[3])
                 : "r"(a[0]), "r"(a[1]), "r"(a[2]), "r"(a[3]), "r"(b[0]), "r"(b[1]));
}
__device__ __forceinline__ unsigned long long pk2(float a, float b) {
    unsigned long long r;
    asm("mov.b64 %0,{%1,%2};" : "=l"(r) : "r"(__float_as_uint(a)), "r"(__float_as_uint(b)));
    return r;
}
__device__ __forceinline__ unsigned long long mulx2(unsigned long long a, unsigned long long b) {
    unsigned long long r;
    asm("mul.rn.f32x2 %0,%1,%2;" : "=l"(r) : "l"(a), "l"(b));
    return r;
}
__device__ __forceinline__ unsigned long long fmax2(unsigned long long a, unsigned long long b, unsigned long long c) {
    unsigned long long r;
    asm("fma.rn.f32x2 %0,%1,%2,%3;" : "=l"(r) : "l"(a), "l"(b), "l"(c));
    return r;
}
__device__ __forceinline__ float upksum(unsigned long long v) {
    uint32_t lo, hi;
    asm("mov.b64 {%0,%1},%2;" : "=r"(lo), "=r"(hi) : "l"(v));
    return __uint_as_float(lo) + __uint_as_float(hi);
}
__device__ __forceinline__ void ldsv2(unsigned long long& a, unsigned long long& b, uint32_t addr) {
    asm volatile("ld.shared.v2.u64 {%0,%1},[%2];" : "=l"(a), "=l"(b) : "r"(addr));
}

// ---------------- RMSNorm (also emits bf16 hi/lo split) -------------------
__global__ __launch_bounds__(256) void rmsnorm_kernel(
    const float* __restrict__ x, const float* __restrict__ w, float* __restrict__ h,
    __nv_bfloat16* __restrict__ hh, __nv_bfloat16* __restrict__ hl)
{
    int row = blockIdx.x;
    int tid = threadIdx.x;
    const float4* xr = (const float4*)(x + (size_t)row * HID_);
    float4 xv = xr[tid];
    float ss = xv.x * xv.x + xv.y * xv.y + xv.z * xv.z + xv.w * xv.w;
    #pragma unroll
    for (int off = 16; off; off >>= 1) ss += __shfl_xor_sync(0xFFFFFFFFu, ss, off);
    __shared__ float red[8];
    __shared__ float rtot;
    int lane = tid & 31, warp = tid >> 5;
    if (lane == 0) red[warp] = ss;
    __syncthreads();
    if (tid == 0) {
        float s = 0.f;
        #pragma unroll
        for (int i = 0; i < 8; i++) s += red[i];
        rtot = rsqrtf(s * (1.0f / HID_) + 1e-6f);
    }
    __syncthreads();
    float r = rtot;
    const float4* wr = (const float4*)w;
    float4 wv = wr[tid];
    float o[4];
    o[0] = xv.x * r * wv.x; o[1] = xv.y * r * wv.y;
    o[2] = xv.z * r * wv.z; o[3] = xv.w * r * wv.w;
    ((float4*)(h + (size_t)row * HID_))[tid] = *(float4*)o;
    __nv_bfloat16 hi[4], lo[4];
    #pragma unroll
    for (int i = 0; i < 4; i++) {
        hi[i] = __float2bfloat16(o[i]);
        lo[i] = __float2bfloat16(o[i] - __bfloat162float(hi[i]));
    }
    size_t base = (size_t)row * HID_;
    ((__nv_bfloat162*)(hh + base))[tid * 2]     = __halves2bfloat162(hi[0], hi[1]);
    ((__nv_bfloat162*)(hh + base))[tid * 2 + 1] = __halves2bfloat162(hi[2], hi[3]);
    ((__nv_bfloat162*)(hl + base))[tid * 2]     = __halves2bfloat162(lo[0], lo[1]);
    ((__nv_bfloat162*)(hl + base))[tid * 2 + 1] = __halves2bfloat162(lo[2], lo[3]);
}

// ---------------- fp32 -> bf16 hi/lo split (weights) -----------------------
__global__ __launch_bounds__(256) void splitf_kernel(
    const float* __restrict__ s, __nv_bfloat16* __restrict__ hi,
    __nv_bfloat16* __restrict__ lo, int n4)
{
    int i = blockIdx.x * blockDim.x + threadIdx.x;
    if (i >= n4) return;
    float4 x = ((const float4*)s)[i];
    float v[4] = {x.x, x.y, x.z, x.w};
    __nv_bfloat16 h[4], l[4];
    #pragma unroll
    for (int j = 0; j < 4; j++) {
        h[j] = __float2bfloat16(v[j]);
        l[j] = __float2bfloat16(v[j] - __bfloat162float(h[j]));
    }
    ((__nv_bfloat162*)hi)[i * 2]     = __halves2bfloat162(h[0], h[1]);
    ((__nv_bfloat162*)hi)[i * 2 + 1] = __halves2bfloat162(h[2], h[3]);
    ((__nv_bfloat162*)lo)[i * 2]     = __halves2bfloat162(l[0], l[1]);
    ((__nv_bfloat162*)lo)[i * 2 + 1] = __halves2bfloat162(l[2], l[3]);
}

// ---------------- bf16-split GEMM: C = A * W^T (+bias), fp32 out ----------
// 3-stage cp.async pipeline. Block 128x128x32, 8 warps, warp 32x64.
// 3-product compensation: Ah*Bh + Ah*Bl + Al*Bh.
#define GTILE 5120               // 128 * 40 bf16 elems per tile
#define GSTAGEB (4 * GTILE * 2)  // bytes per stage (Ah,Al,Bh,Bl) = 40960
#define GNST 3
#define GSMEM (GNST * GSTAGEB)   // 122880 bytes

__global__ __launch_bounds__(256) void gemm_bf16x2(
    const __nv_bfloat16* __restrict__ Ah, const __nv_bfloat16* __restrict__ Al,
    const __nv_bfloat16* __restrict__ Bh, const __nv_bfloat16* __restrict__ Bl,
    const float* __restrict__ bias, float* __restrict__ C,
    int M, int N, int K)
{
    extern __shared__ __nv_bfloat16 sm[];
    uint32_t sbase = s2u(sm);
    int tid = threadIdx.x;
    int bm = blockIdx.y, bn = blockIdx.x;
    int w = tid >> 5, lane = tid & 31;
    int wm = (w & 3) * 32, wn = (w >> 2) * 64;
    int g = lane >> 2, tq = lane & 3;

    const __nv_bfloat16* srcs[4];
    srcs[0] = Ah + (size_t)(bm * 128) * K;
    srcs[1] = Al + (size_t)(bm * 128) * K;
    srcs[2] = Bh + (size_t)(bn * 128) * K;
    srcs[3] = Bl + (size_t)(bn * 128) * K;

    float acc[2][8][4];
    #pragma unroll
    for (int i = 0; i < 2; i++)
        #pragma unroll
        for (int j = 0; j < 8; j++)
            #pragma unroll
            for (int q = 0; q < 4; q++) acc[i][j][q] = 0.f;

    int rA = (lane & 7) + ((lane & 8) ? 8 : 0);
    int cA = (lane & 16) ? 8 : 0;
    int rB = (lane & 7) + ((lane & 16) ? 8 : 0);
    int cB = (lane & 8) ? 8 : 0;

    auto loadStage = [&](int st, int k0) {
        #pragma unroll
        for (int mtx = 0; mtx < 4; mtx++) {
            uint32_t dbase = sbase + st * GSTAGEB + mtx * (GTILE * 2);
            const __nv_bfloat16* s = srcs[mtx] + k0;
            #pragma unroll
            for (int rep = 0; rep < 2; rep++) {
                int j = tid + rep * 256;
                int row = j >> 2, cc = j & 3;
                cp16(dbase + row * 80 + cc * 16, s + (size_t)row * K + cc * 8);
            }
        }
    };

    loadStage(0, 0);  cp_commit();
    loadStage(1, 32); cp_commit();

    int niter = K / 32;
    for (int it = 0; it < niter; it++) {
        int cur = it % GNST;
        if (it == niter - 1) asm volatile("cp.async.wait_group 0;");
        else                 asm volatile("cp.async.wait_group 1;");
        __syncthreads();
        if (it + 2 < niter) { loadStage((it + 2) % GNST, (it + 2) * 32); cp_commit(); }

        uint32_t stb = sbase + cur * GSTAGEB;
        #pragma unroll
        for (int ks = 0; ks < 2; ks++) {
            int kb = ks * 16;
            uint32_t a_h[2][4], a_l[2][4];
            #pragma unroll
            for (int mi = 0; mi < 2; mi++) {
                uint32_t ad = stb + ((wm + mi * 16 + rA) * 40 + kb + cA) * 2;
                ldsm4(a_h[mi], ad);
                ldsm4(a_l[mi], ad + GTILE * 2);
            }
            #pragma unroll
            for (int np = 0; np < 4; np++) {
                uint32_t bd = stb + 2 * GTILE * 2 + ((wn + np * 16 + rB) * 40 + kb + cB) * 2;
                uint32_t b_h[4], b_l[4];
                ldsm4(b_h, bd);
                ldsm4(b_l, bd + GTILE * 2);
                #pragma unroll
                for (int mi = 0; mi < 2; mi++) {
                    mma16816(acc[mi][np * 2],     a_h[mi], b_h);
                    mma16816(acc[mi][np * 2 + 1], a_h[mi], b_h + 2);
                    mma16816(acc[mi][np * 2],     a_h[mi], b_l);
                    mma16816(acc[mi][np * 2 + 1], a_h[mi], b_l + 2);
                    mma16816(acc[mi][np * 2],     a_l[mi], b_h);
                    mma16816(acc[mi][np * 2 + 1], a_l[mi], b_h + 2);
                }
            }
        }
    }

    int rowb = bm * 128 + wm;
    int colb = bn * 128 + wn;
    #pragma unroll
    for (int mi = 0; mi < 2; mi++) {
        int r0 = rowb + mi * 16 + g;
        #pragma unroll
        for (int nj = 0; nj < 8; nj++) {
            int cc = colb + nj * 8 + tq * 2;
            float bx = 0.f, by = 0.f;
            if (bias) { float2 b2 = *(const float2*)(bias + cc); bx = b2.x; by = b2.y; }
            float2 o0, o1;
            o0.x = acc[mi][nj][0] + bx; o0.y = acc[mi][nj][1] + by;
            o1.x = acc[mi][nj][2] + bx; o1.y = acc[mi][nj][3] + by;
            *(float2*)(C + (size_t)r0 * N + cc) = o0;
            *(float2*)(C + (size_t)(r0 + 8) * N + cc) = o1;
        }
    }
}

// ---------------- Gates ----------------------------------------------------
__global__ __launch_bounds__(256) void gates_kernel(
    const float* __restrict__ h,
    const float* __restrict__ Wb, const float* __restrict__ bb,
    const float* __restrict__ Wi, const float* __restrict__ bi,
    const float* __restrict__ Wo, const float* __restrict__ bo,
    float* __restrict__ gates)
{
    int row = blockIdx.x;
    int tid = threadIdx.x;
    __shared__ float hs[HID_];
    const float* hr = h + (size_t)row * HID_;
    for (int i = tid; i < HID_; i += 256) hs[i] = hr[i];
    __syncthreads();
    int w = tid >> 5, lane = tid & 31;
    int b = row / L_, t = row % L_;
    const float* Ws[3] = {Wb, Wi, Wo};
    const float* bs[3] = {bb, bi, bo};
    #pragma unroll
    for (int gt = 0; gt < 3; gt++) {
        const float* wrow = Ws[gt] + w * HID_;
        float sum = 0.f;
        for (int i = lane; i < HID_; i += 32) sum += hs[i] * wrow[i];
        #pragma unroll
        for (int off = 16; off; off >>= 1) sum += __shfl_xor_sync(0xFFFFFFFFu, sum, off);
        if (lane == 0) {
            float val = 1.f / (1.f + expf(-(sum + bs[gt][w])));
            gates[(size_t)gt * (B_ * NH_ * L_) + (size_t)(b * NH_ + w) * L_ + t] = val;
        }
    }
}

// ---------------- RoPE tables ---------------------------------------------
__global__ void rope_table_kernel(float* __restrict__ tab)
{
    int idx = blockIdx.x * blockDim.x + threadIdx.x;
    if (idx >= L_ * HALF_) return;
    int t = idx >> 6, j = idx & 63;
    double invf = exp(-(double)j / 64.0 * 9.210340371976182736);
    float ang = (float)t * (float)invf;
    tab[idx] = (float)cos((double)ang);
    tab[L_ * HALF_ + idx] = (float)sin((double)ang);
}

// ---------------- RoPE apply ----------------------------------------------
__global__ __launch_bounds__(512) void rope_apply_kernel(
    float* __restrict__ q, float* __restrict__ k, const float* __restrict__ tab)
{
    int row = blockIdx.x;
    int t = row % L_;
    int tid = threadIdx.x;
    int hh = tid >> 6, j = tid & 63;
    size_t base = (size_t)row * HID_ + hh * DH_;
    float c = tab[t * HALF_ + j];
    float s = tab[L_ * HALF_ + t * HALF_ + j];
    float q1 = q[base + j], q2 = q[base + HALF_ + j];
    q[base + j]          = q1 * c - q2 * s;
    q[base + HALF_ + j]  = q1 * s + q2 * c;
    float k1 = k[base + j], k2 = k[base + HALF_ + j];
    k[base + j]          = k1 * c - k2 * s;
    k[base + HALF_ + j]  = k1 * s + k2 * c;
}

// ---------------- Recurrence: 8 blocks per (b,h), 16 cols each -------------
// thread (c, rg): owns M[rg*16 .. rg*16+15][col0+c]; 128 threads = 16c x 8rg.
// Per-step partial dot products go to smem; reduced every 16 steps (no shfl
// chain on the per-step critical path).
#define NSTG 8
#define STGF 340       // floats per stage: q 8x20, k 8x20, v 16, fgo 4
__global__ __launch_bounds__(128) void recurrence2_kernel(
    const float* __restrict__ q, const float* __restrict__ k,
    const float* __restrict__ v, const float* __restrict__ gates,
    __nv_bfloat16* __restrict__ yh, __nv_bfloat16* __restrict__ yl)
{
    __shared__ float rs[NSTG * STGF];
    __shared__ __align__(16) float pp[16 * 128];
    __shared__ float ow[16];
    int split = blockIdx.x, bh = blockIdx.y;
    int b = bh >> 3, hh = bh & 7;
    int tid = threadIdx.x;
    int c = tid >> 3, rg = tid & 7;
    int col0 = split * 16;
    size_t headbase = (size_t)b * L_ * HID_ + hh * DH_;
    const float* fp = gates + (size_t)bh * L_;
    const float* gp = fp + (size_t)(B_ * NH_) * L_;
    const float* op = gp + (size_t)(B_ * NH_) * L_;
    uint32_t sb = s2u(rs);

    auto issue = [&](int t) {
        if (t >= L_) return;
        uint32_t base = sb + (t & (NSTG - 1)) * (STGF * 4);
        size_t row = headbase + (size_t)t * HID_;
        if (tid < 32) {
            cp16(base + (tid >> 2) * 80 + (tid & 3) * 16, q + row + tid * 4);
        } else if (tid < 64) {
            int j = tid - 32;
            cp16(base + 640 + (j >> 2) * 80 + (j & 3) * 16, k + row + j * 4);
        } else if (tid < 68) {
            int j = tid - 64;
            cp16(base + 1280 + j * 16, v + row + col0 + j * 4);
        } else if (tid < 71) {
            int j = tid - 68;
            const float* p = (j == 0 ? fp : (j == 1 ? gp : op)) + t;
            cp4(base + 1344 + j * 4, p);
        }
    };

    for (int t = 0; t < 7; t++) { issue(t); cp_commit(); }

    unsigned long long M2[8];
    #pragma unroll
    for (int i = 0; i < 8; i++) M2[i] = 0ull;

    for (int t = 0; t < L_; t++) {
        int st = t & (NSTG - 1);
        asm volatile("cp.async.wait_group 6;");
        __syncthreads();
        float ff = rs[st * STGF + 336];
        float gg = rs[st * STGF + 337];
        float vv = rs[st * STGF + 320 + c];
        if (tid == 0) ow[t & 15] = rs[st * STGF + 338];
        float c1 = gg * SCALE_ * vv;
        unsigned long long ffp = pk2(ff, ff);
        unsigned long long c1p = pk2(c1, c1);
        unsigned long long p2 = 0ull;
        uint32_t qa = sb + st * (STGF * 4) + rg * 80;
        uint32_t ka = qa + 640;
        #pragma unroll
        for (int i = 0; i < 4; i++) {
            unsigned long long k0, k1, q0, q1, t0;
            ldsv2(k0, k1, ka + i * 16);
            ldsv2(q0, q1, qa + i * 16);
            t0 = mulx2(c1p, k0);
            M2[2 * i] = fmax2(M2[2 * i], ffp, t0);
            p2 = fmax2(q0, M2[2 * i], p2);
            t0 = mulx2(c1p, k1);
            M2[2 * i + 1] = fmax2(M2[2 * i + 1], ffp, t0);
            p2 = fmax2(q1, M2[2 * i + 1], p2);
        }
        pp[(t & 15) * 128 + c * 8 + rg] = upksum(p2);
        issue(t + 7);
        cp_commit();
        if ((t & 15) == 15) {
            __syncthreads();
            int t0i = t - 15;
            #pragma unroll
            for (int r2 = 0; r2 < 2; r2++) {
                int oidx = tid + r2 * 128;
                int tt = oidx >> 4, ci = oidx & 15;
                float4 va = *(float4*)&pp[tt * 128 + ci * 8];
                float4 vb = *(float4*)&pp[tt * 128 + ci * 8 + 4];
                float s = ((va.x + va.y) + (va.z + va.w)) + ((vb.x + vb.y) + (vb.z + vb.w));
                float yv = ow[tt] * s;
                size_t yi = headbase + (size_t)(t0i + tt) * HID_ + col0 + ci;
                __nv_bfloat16 h16 = __float2bfloat16(yv);
                yh[yi] = h16;
                yl[yi] = __float2bfloat16(yv - __bfloat162float(h16));
            }
        }
    }
}

// ---------------- launch ---------------------------------------------------
extern "C" void kernel_launch(void* const* d_in, const int* in_sizes, int n_in,
                              void* d_out, int out_size)
{
    const float* x      = (const float*)d_in[0];
    const float* norm_w = (const float*)d_in[1];
    const float* Wq     = (const float*)d_in[2];
    const float* Wk     = (const float*)d_in[3];
    const float* Wv     = (const float*)d_in[4];
    const float* Wbeta  = (const float*)d_in[5];
    const float* bbeta  = (const float*)d_in[6];
    const float* Wig    = (const float*)d_in[7];
    const float* big    = (const float*)d_in[8];
    const float* Wog    = (const float*)d_in[9];
    const float* bog    = (const float*)d_in[10];
    const float* Wout   = (const float*)d_in[11];
    const float* bout   = (const float*)d_in[12];
    float* out = (float*)d_out;

    float *hbuf, *qb, *kb, *vb, *gb, *rt;
    __nv_bfloat16 *hh, *hl, *yh, *yl, *wh, *wl;
    cudaGetSymbolAddress((void**)&hbuf, g_h);
    cudaGetSymbolAddress((void**)&hh,   g_hh);
    cudaGetSymbolAddress((void**)&hl,   g_hl);
    cudaGetSymbolAddress((void**)&qb,   g_q);
    cudaGetSymbolAddress((void**)&kb,   g_k);
    cudaGetSymbolAddress((void**)&vb,   g_v);
    cudaGetSymbolAddress((void**)&yh,   g_yh);
    cudaGetSymbolAddress((void**)&yl,   g_yl);
    cudaGetSymbolAddress((void**)&wh,   g_wh);
    cudaGetSymbolAddress((void**)&wl,   g_wl);
    cudaGetSymbolAddress((void**)&gb,   g_gates);
    cudaGetSymbolAddress((void**)&rt,   g_rope);

    cudaFuncSetAttribute(gemm_bf16x2, cudaFuncAttributeMaxDynamicSharedMemorySize, GSMEM);

    const size_t WSZ = (size_t)HID_ * HID_;
    const int n4 = (int)(WSZ / 4);
    dim3 ggrid(HID_ / 128, ROWS_ / 128);

    rmsnorm_kernel<<<ROWS_, 256>>>(x, norm_w, hbuf, hh, hl);                        // 0
    splitf_kernel<<<(n4 + 255) / 256, 256>>>(Wq,   wh,           wl,           n4); // 1
    splitf_kernel<<<(n4 + 255) / 256, 256>>>(Wk,   wh + WSZ,     wl + WSZ,     n4); // 2
    splitf_kernel<<<(n4 + 255) / 256, 256>>>(Wv,   wh + 2 * WSZ, wl + 2 * WSZ, n4); // 3
    splitf_kernel<<<(n4 + 255) / 256, 256>>>(Wout, wh + 3 * WSZ, wl + 3 * WSZ, n4); // 4

    gemm_bf16x2<<<ggrid, 256, GSMEM>>>(hh, hl, wh,           wl,           nullptr, qb, ROWS_, HID_, HID_); // 5 (profiled)
    gemm_bf16x2<<<ggrid, 256, GSMEM>>>(hh, hl, wh + WSZ,     wl + WSZ,     nullptr, kb, ROWS_, HID_, HID_); // 6
    gemm_bf16x2<<<ggrid, 256, GSMEM>>>(hh, hl, wh + 2 * WSZ, wl + 2 * WSZ, nullptr, vb, ROWS_, HID_, HID_); // 7

    gates_kernel<<<ROWS_, 256>>>(hbuf, Wbeta, bbeta, Wig, big, Wog, bog, gb);

    rope_table_kernel<<<(L_ * HALF_ + 255) / 256, 256>>>(rt);
    rope_apply_kernel<<<ROWS_, 512>>>(qb, kb, rt);

    recurrence2_kernel<<<dim3(8, B_ * NH_), 128>>>(qb, kb, vb, gb, yh, yl);

    gemm_bf16x2<<<ggrid, 256, GSMEM>>>(yh, yl, wh + 3 * WSZ, wl + 3 * WSZ, bout, out, ROWS_, HID_, HID_);
}

// round 7
// speedup vs baseline: 2.3387x; 1.0644x over previous
#include <cuda_runtime.h>
#include <cuda_bf16.h>
#include <math.h>
#include <stdint.h>

#define B_  4
#define L_  4096
#define HID_ 1024
#define NH_ 8
#define DH_ 128
#define HALF_ 64
#define ROWS_ (B_ * L_)          // 16384
#define SCALE_ 0.08838834764831845f  // 1/sqrt(128)

// ---------------- scratch (static device globals: allocation-free) ----------
__device__ float g_h[(size_t)ROWS_ * HID_];
__device__ __nv_bfloat16 g_hh[(size_t)ROWS_ * HID_];
__device__ __nv_bfloat16 g_hl[(size_t)ROWS_ * HID_];
__device__ float g_q[(size_t)ROWS_ * HID_];
__device__ float g_k[(size_t)ROWS_ * HID_];
__device__ float g_v[(size_t)ROWS_ * HID_];
__device__ __nv_bfloat16 g_yh[(size_t)ROWS_ * HID_];
__device__ __nv_bfloat16 g_yl[(size_t)ROWS_ * HID_];
__device__ __nv_bfloat16 g_wh[(size_t)4 * HID_ * HID_];
__device__ __nv_bfloat16 g_wl[(size_t)4 * HID_ * HID_];
__device__ float g_gates[3 * B_ * NH_ * L_];
__device__ float g_rope[2 * L_ * HALF_];

// ---------------- helpers -------------------------------------------------
__device__ __forceinline__ uint32_t s2u(const void* p) {
    return (uint32_t)__cvta_generic_to_shared(p);
}
__device__ __forceinline__ void cp16(uint32_t d, const void* p) {
    asm volatile("cp.async.cg.shared.global [%0],[%1],16;" :: "r"(d), "l"(p));
}
__device__ __forceinline__ void cp4(uint32_t d, const void* p) {
    asm volatile("cp.async.ca.shared.global [%0],[%1],4;" :: "r"(d), "l"(p));
}
__device__ __forceinline__ void cp_commit() {
    asm volatile("cp.async.commit_group;");
}
__device__ __forceinline__ void ldsm4(uint32_t* r, uint32_t a) {
    asm volatile("ldmatrix.sync.aligned.m8n8.x4.shared.b16 {%0,%1,%2,%3},[%4];"
                 : "=r"(r[0]), "=r"(r[1]), "=r"(r[2]), "=r"(r[3]) : "r"(a));
}
__device__ __forceinline__ void mma16816(float* c, const uint32_t* a, const uint32_t* b) {
    asm volatile("mma.sync.aligned.m16n8k16.row.col.f32.bf16.bf16.f32 "
                 "{%0,%1,%2,%3},{%4,%5,%6,%7},{%8,%9},{%0,%1,%2,%3};"
                 : "+f"(c[0]), "+f"(c[1]), "+f"(c[2]), "+f"(c[3])
                 : "r"(a[0]), "r"(a[1]), "r"(a[2]), "r"(a[3]), "r"(b[0]), "r"(b[1]));
}
__device__ __forceinline__ unsigned long long pk2(float a, float b) {
    unsigned long long r;
    asm("mov.b64 %0,{%1,%2};" : "=l"(r) : "r"(__float_as_uint(a)), "r"(__float_as_uint(b)));
    return r;
}
__device__ __forceinline__ unsigned long long mulx2(unsigned long long a, unsigned long long b) {
    unsigned long long r;
    asm("mul.rn.f32x2 %0,%1,%2;" : "=l"(r) : "l"(a), "l"(b));
    return r;
}
__device__ __forceinline__ unsigned long long fmax2(unsigned long long a, unsigned long long b, unsigned long long c) {
    unsigned long long r;
    asm("fma.rn.f32x2 %0,%1,%2,%3;" : "=l"(r) : "l"(a), "l"(b), "l"(c));
    return r;
}
__device__ __forceinline__ float upksum(unsigned long long v) {
    uint32_t lo, hi;
    asm("mov.b64 {%0,%1},%2;" : "=r"(lo), "=r"(hi) : "l"(v));
    return __uint_as_float(lo) + __uint_as_float(hi);
}
__device__ __forceinline__ void ldsv2(unsigned long long& a, unsigned long long& b, uint32_t addr) {
    asm volatile("ld.shared.v2.u64 {%0,%1},[%2];" : "=l"(a), "=l"(b) : "r"(addr));
}

// ---------------- RMSNorm (also emits bf16 hi/lo split) -------------------
__global__ __launch_bounds__(256) void rmsnorm_kernel(
    const float* __restrict__ x, const float* __restrict__ w, float* __restrict__ h,
    __nv_bfloat16* __restrict__ hh, __nv_bfloat16* __restrict__ hl)
{
    int row = blockIdx.x;
    int tid = threadIdx.x;
    const float4* xr = (const float4*)(x + (size_t)row * HID_);
    float4 xv = xr[tid];
    float ss = xv.x * xv.x + xv.y * xv.y + xv.z * xv.z + xv.w * xv.w;
    #pragma unroll
    for (int off = 16; off; off >>= 1) ss += __shfl_xor_sync(0xFFFFFFFFu, ss, off);
    __shared__ float red[8];
    __shared__ float rtot;
    int lane = tid & 31, warp = tid >> 5;
    if (lane == 0) red[warp] = ss;
    __syncthreads();
    if (tid == 0) {
        float s = 0.f;
        #pragma unroll
        for (int i = 0; i < 8; i++) s += red[i];
        rtot = rsqrtf(s * (1.0f / HID_) + 1e-6f);
    }
    __syncthreads();
    float r = rtot;
    const float4* wr = (const float4*)w;
    float4 wv = wr[tid];
    float o[4];
    o[0] = xv.x * r * wv.x; o[1] = xv.y * r * wv.y;
    o[2] = xv.z * r * wv.z; o[3] = xv.w * r * wv.w;
    ((float4*)(h + (size_t)row * HID_))[tid] = *(float4*)o;
    __nv_bfloat16 hi[4], lo[4];
    #pragma unroll
    for (int i = 0; i < 4; i++) {
        hi[i] = __float2bfloat16(o[i]);
        lo[i] = __float2bfloat16(o[i] - __bfloat162float(hi[i]));
    }
    size_t base = (size_t)row * HID_;
    ((__nv_bfloat162*)(hh + base))[tid * 2]     = __halves2bfloat162(hi[0], hi[1]);
    ((__nv_bfloat162*)(hh + base))[tid * 2 + 1] = __halves2bfloat162(hi[2], hi[3]);
    ((__nv_bfloat162*)(hl + base))[tid * 2]     = __halves2bfloat162(lo[0], lo[1]);
    ((__nv_bfloat162*)(hl + base))[tid * 2 + 1] = __halves2bfloat162(lo[2], lo[3]);
}

// ---------------- fp32 -> bf16 hi/lo split (weights) -----------------------
__global__ __launch_bounds__(256) void splitf_kernel(
    const float* __restrict__ s, __nv_bfloat16* __restrict__ hi,
    __nv_bfloat16* __restrict__ lo, int n4)
{
    int i = blockIdx.x * blockDim.x + threadIdx.x;
    if (i >= n4) return;
    float4 x = ((const float4*)s)[i];
    float v[4] = {x.x, x.y, x.z, x.w};
    __nv_bfloat16 h[4], l[4];
    #pragma unroll
    for (int j = 0; j < 4; j++) {
        h[j] = __float2bfloat16(v[j]);
        l[j] = __float2bfloat16(v[j] - __bfloat162float(h[j]));
    }
    ((__nv_bfloat162*)hi)[i * 2]     = __halves2bfloat162(h[0], h[1]);
    ((__nv_bfloat162*)hi)[i * 2 + 1] = __halves2bfloat162(h[2], h[3]);
    ((__nv_bfloat162*)lo)[i * 2]     = __halves2bfloat162(l[0], l[1]);
    ((__nv_bfloat162*)lo)[i * 2 + 1] = __halves2bfloat162(l[2], l[3]);
}

// ---------------- bf16-split GEMM: C = A * W^T (+bias), fp32 out ----------
// 2-stage cp.async pipeline, 2 CTAs/SM. Block 128x128x32, 8 warps, warp 32x64.
// 3-product compensation: Ah*Bh + Ah*Bl + Al*Bh.
#define GTILE 5120               // 128 * 40 bf16 elems per tile
#define GSTAGEB (4 * GTILE * 2)  // bytes per stage (Ah,Al,Bh,Bl) = 40960
#define GNST 2
#define GSMEM (GNST * GSTAGEB)   // 81920 bytes

__global__ __launch_bounds__(256, 2) void gemm_bf16x2(
    const __nv_bfloat16* __restrict__ Ah, const __nv_bfloat16* __restrict__ Al,
    const __nv_bfloat16* __restrict__ Bh, const __nv_bfloat16* __restrict__ Bl,
    const float* __restrict__ bias, float* __restrict__ C,
    int M, int N, int K)
{
    extern __shared__ __nv_bfloat16 sm[];
    uint32_t sbase = s2u(sm);
    int tid = threadIdx.x;
    int bm = blockIdx.y, bn = blockIdx.x;
    int w = tid >> 5, lane = tid & 31;
    int wm = (w & 3) * 32, wn = (w >> 2) * 64;
    int g = lane >> 2, tq = lane & 3;

    const __nv_bfloat16* srcs[4];
    srcs[0] = Ah + (size_t)(bm * 128) * K;
    srcs[1] = Al + (size_t)(bm * 128) * K;
    srcs[2] = Bh + (size_t)(bn * 128) * K;
    srcs[3] = Bl + (size_t)(bn * 128) * K;

    float acc[2][8][4];
    #pragma unroll
    for (int i = 0; i < 2; i++)
        #pragma unroll
        for (int j = 0; j < 8; j++)
            #pragma unroll
            for (int q = 0; q < 4; q++) acc[i][j][q] = 0.f;

    int rA = (lane & 7) + ((lane & 8) ? 8 : 0);
    int cA = (lane & 16) ? 8 : 0;
    int rB = (lane & 7) + ((lane & 16) ? 8 : 0);
    int cB = (lane & 8) ? 8 : 0;

    auto loadStage = [&](int st, int k0) {
        #pragma unroll
        for (int mtx = 0; mtx < 4; mtx++) {
            uint32_t dbase = sbase + st * GSTAGEB + mtx * (GTILE * 2);
            const __nv_bfloat16* s = srcs[mtx] + k0;
            #pragma unroll
            for (int rep = 0; rep < 2; rep++) {
                int j = tid + rep * 256;
                int row = j >> 2, cc = j & 3;
                cp16(dbase + row * 80 + cc * 16, s + (size_t)row * K + cc * 8);
            }
        }
    };

    loadStage(0, 0); cp_commit();

    int niter = K / 32;
    for (int it = 0; it < niter; it++) {
        int cur = it & 1;
        if (it + 1 < niter) {
            loadStage((it + 1) & 1, (it + 1) * 32); cp_commit();
            asm volatile("cp.async.wait_group 1;");
        } else {
            asm volatile("cp.async.wait_group 0;");
        }
        __syncthreads();

        uint32_t stb = sbase + cur * GSTAGEB;
        #pragma unroll
        for (int ks = 0; ks < 2; ks++) {
            int kb = ks * 16;
            uint32_t a_h[2][4], a_l[2][4];
            #pragma unroll
            for (int mi = 0; mi < 2; mi++) {
                uint32_t ad = stb + ((wm + mi * 16 + rA) * 40 + kb + cA) * 2;
                ldsm4(a_h[mi], ad);
                ldsm4(a_l[mi], ad + GTILE * 2);
            }
            #pragma unroll
            for (int np = 0; np < 4; np++) {
                uint32_t bd = stb + 2 * GTILE * 2 + ((wn + np * 16 + rB) * 40 + kb + cB) * 2;
                uint32_t b_h[4], b_l[4];
                ldsm4(b_h, bd);
                ldsm4(b_l, bd + GTILE * 2);
                #pragma unroll
                for (int mi = 0; mi < 2; mi++) {
                    mma16816(acc[mi][np * 2],     a_h[mi], b_h);
                    mma16816(acc[mi][np * 2 + 1], a_h[mi], b_h + 2);
                    mma16816(acc[mi][np * 2],     a_h[mi], b_l);
                    mma16816(acc[mi][np * 2 + 1], a_h[mi], b_l + 2);
                    mma16816(acc[mi][np * 2],     a_l[mi], b_h);
                    mma16816(acc[mi][np * 2 + 1], a_l[mi], b_h + 2);
                }
            }
        }
        __syncthreads();   // all warps done reading 'cur' before it is overwritten
    }

    int rowb = bm * 128 + wm;
    int colb = bn * 128 + wn;
    #pragma unroll
    for (int mi = 0; mi < 2; mi++) {
        int r0 = rowb + mi * 16 + g;
        #pragma unroll
        for (int nj = 0; nj < 8; nj++) {
            int cc = colb + nj * 8 + tq * 2;
            float bx = 0.f, by = 0.f;
            if (bias) { float2 b2 = *(const float2*)(bias + cc); bx = b2.x; by = b2.y; }
            float2 o0, o1;
            o0.x = acc[mi][nj][0] + bx; o0.y = acc[mi][nj][1] + by;
            o1.x = acc[mi][nj][2] + bx; o1.y = acc[mi][nj][3] + by;
            *(float2*)(C + (size_t)r0 * N + cc) = o0;
            *(float2*)(C + (size_t)(r0 + 8) * N + cc) = o1;
        }
    }
}

// ---------------- Gates as tiled mini-GEMM: 128 rows x 24 outputs ----------
// block = 128 threads, thread = one row. Weights staged per 64-K chunk.
// NOTE: hs rows use stride 65 (conflict-free reads); smem writes are scalar
// stores (float4 store at odd-row stride-65 would be misaligned).
__global__ __launch_bounds__(128) void gates2_kernel(
    const float* __restrict__ h,
    const float* __restrict__ Wb, const float* __restrict__ bb,
    const float* __restrict__ Wi, const float* __restrict__ bi,
    const float* __restrict__ Wo, const float* __restrict__ bo,
    float* __restrict__ gates)
{
    __shared__ float hs[128 * 65];
    __shared__ float ws[24 * 64];
    int tid = threadIdx.x;
    int r0 = blockIdx.x * 128;

    float acc[24];
    #pragma unroll
    for (int c = 0; c < 24; c++) acc[c] = 0.f;

    for (int k0 = 0; k0 < HID_; k0 += 64) {
        // cooperative coalesced load of h tile [128][64] (scalar smem stores)
        #pragma unroll
        for (int i = 0; i < 16; i++) {
            int idx = tid + i * 128;          // float4 index among 2048
            int row = idx >> 4, c4 = idx & 15;
            float4 v = *(const float4*)(h + (size_t)(r0 + row) * HID_ + k0 + c4 * 4);
            float* d = &hs[row * 65 + c4 * 4];
            d[0] = v.x; d[1] = v.y; d[2] = v.z; d[3] = v.w;
        }
        // weight tile [24][64]: rows 0-7 Wb, 8-15 Wi, 16-23 Wo
        #pragma unroll
        for (int i = 0; i < 3; i++) {
            int idx = tid + i * 128;          // float4 index among 384
            int c = idx >> 4, j4 = idx & 15;
            const float* src = (c < 8 ? Wb + c * HID_
                               : c < 16 ? Wi + (c - 8) * HID_
                                        : Wo + (c - 16) * HID_);
            float4 v = *(const float4*)(src + k0 + j4 * 4);
            float* d = &ws[c * 64 + j4 * 4];
            d[0] = v.x; d[1] = v.y; d[2] = v.z; d[3] = v.w;
        }
        __syncthreads();
        #pragma unroll 4
        for (int j = 0; j < 64; j++) {
            float hj = hs[tid * 65 + j];
            #pragma unroll
            for (int c = 0; c < 24; c++) acc[c] += hj * ws[c * 64 + j];
        }
        __syncthreads();
    }

    int row = r0 + tid;
    int b = row >> 12, t = row & 4095;
    #pragma unroll
    for (int gt = 0; gt < 3; gt++) {
        const float* bias = (gt == 0 ? bb : gt == 1 ? bi : bo);
        #pragma unroll
        for (int hd = 0; hd < 8; hd++) {
            float val = 1.f / (1.f + expf(-(acc[gt * 8 + hd] + bias[hd])));
            gates[(size_t)gt * (B_ * NH_ * L_) + (size_t)(b * NH_ + hd) * L_ + t] = val;
        }
    }
}

// ---------------- RoPE tables ---------------------------------------------
__global__ void rope_table_kernel(float* __restrict__ tab)
{
    int idx = blockIdx.x * blockDim.x + threadIdx.x;
    if (idx >= L_ * HALF_) return;
    int t = idx >> 6, j = idx & 63;
    double invf = exp(-(double)j / 64.0 * 9.210340371976182736);
    float ang = (float)t * (float)invf;
    tab[idx] = (float)cos((double)ang);
    tab[L_ * HALF_ + idx] = (float)sin((double)ang);
}

// ---------------- RoPE apply ----------------------------------------------
__global__ __launch_bounds__(512) void rope_apply_kernel(
    float* __restrict__ q, float* __restrict__ k, const float* __restrict__ tab)
{
    int row = blockIdx.x;
    int t = row % L_;
    int tid = threadIdx.x;
    int hh = tid >> 6, j = tid & 63;
    size_t base = (size_t)row * HID_ + hh * DH_;
    float c = tab[t * HALF_ + j];
    float s = tab[L_ * HALF_ + t * HALF_ + j];
    float q1 = q[base + j], q2 = q[base + HALF_ + j];
    q[base + j]          = q1 * c - q2 * s;
    q[base + HALF_ + j]  = q1 * s + q2 * c;
    float k1 = k[base + j], k2 = k[base + HALF_ + j];
    k[base + j]          = k1 * c - k2 * s;
    k[base + HALF_ + j]  = k1 * s + k2 * c;
}

// ---------------- Recurrence: 8 blocks per (b,h), 16 cols each -------------
#define NSTG 8
#define STGF 340       // floats per stage: q 8x20, k 8x20, v 16, fgo 4
__global__ __launch_bounds__(128) void recurrence2_kernel(
    const float* __restrict__ q, const float* __restrict__ k,
    const float* __restrict__ v, const float* __restrict__ gates,
    __nv_bfloat16* __restrict__ yh, __nv_bfloat16* __restrict__ yl)
{
    __shared__ float rs[NSTG * STGF];
    __shared__ __align__(16) float pp[16 * 128];
    __shared__ float ow[16];
    int split = blockIdx.x, bh = blockIdx.y;
    int b = bh >> 3, hh = bh & 7;
    int tid = threadIdx.x;
    int c = tid >> 3, rg = tid & 7;
    int col0 = split * 16;
    size_t headbase = (size_t)b * L_ * HID_ + hh * DH_;
    const float* fp = gates + (size_t)bh * L_;
    const float* gp = fp + (size_t)(B_ * NH_) * L_;
    const float* op = gp + (size_t)(B_ * NH_) * L_;
    uint32_t sb = s2u(rs);

    auto issue = [&](int t) {
        if (t >= L_) return;
        uint32_t base = sb + (t & (NSTG - 1)) * (STGF * 4);
        size_t row = headbase + (size_t)t * HID_;
        if (tid < 32) {
            cp16(base + (tid >> 2) * 80 + (tid & 3) * 16, q + row + tid * 4);
        } else if (tid < 64) {
            int j = tid - 32;
            cp16(base + 640 + (j >> 2) * 80 + (j & 3) * 16, k + row + j * 4);
        } else if (tid < 68) {
            int j = tid - 64;
            cp16(base + 1280 + j * 16, v + row + col0 + j * 4);
        } else if (tid < 71) {
            int j = tid - 68;
            const float* p = (j == 0 ? fp : (j == 1 ? gp : op)) + t;
            cp4(base + 1344 + j * 4, p);
        }
    };

    for (int t = 0; t < 7; t++) { issue(t); cp_commit(); }

    unsigned long long M2[8];
    #pragma unroll
    for (int i = 0; i < 8; i++) M2[i] = 0ull;

    for (int t = 0; t < L_; t++) {
        int st = t & (NSTG - 1);
        asm volatile("cp.async.wait_group 6;");
        __syncthreads();
        float ff = rs[st * STGF + 336];
        float gg = rs[st * STGF + 337];
        float vv = rs[st * STGF + 320 + c];
        if (tid == 0) ow[t & 15] = rs[st * STGF + 338];
        float c1 = gg * SCALE_ * vv;
        unsigned long long ffp = pk2(ff, ff);
        unsigned long long c1p = pk2(c1, c1);
        unsigned long long p2 = 0ull;
        uint32_t qa = sb + st * (STGF * 4) + rg * 80;
        uint32_t ka = qa + 640;
        #pragma unroll
        for (int i = 0; i < 4; i++) {
            unsigned long long k0, k1, q0, q1, t0;
            ldsv2(k0, k1, ka + i * 16);
            ldsv2(q0, q1, qa + i * 16);
            t0 = mulx2(c1p, k0);
            M2[2 * i] = fmax2(M2[2 * i], ffp, t0);
            p2 = fmax2(q0, M2[2 * i], p2);
            t0 = mulx2(c1p, k1);
            M2[2 * i + 1] = fmax2(M2[2 * i + 1], ffp, t0);
            p2 = fmax2(q1, M2[2 * i + 1], p2);
        }
        pp[(t & 15) * 128 + c * 8 + rg] = upksum(p2);
        issue(t + 7);
        cp_commit();
        if ((t & 15) == 15) {
            __syncthreads();
            int t0i = t - 15;
            #pragma unroll
            for (int r2 = 0; r2 < 2; r2++) {
                int oidx = tid + r2 * 128;
                int tt = oidx >> 4, ci = oidx & 15;
                float4 va = *(float4*)&pp[tt * 128 + ci * 8];
                float4 vb = *(float4*)&pp[tt * 128 + ci * 8 + 4];
                float s = ((va.x + va.y) + (va.z + va.w)) + ((vb.x + vb.y) + (vb.z + vb.w));
                float yv = ow[tt] * s;
                size_t yi = headbase + (size_t)(t0i + tt) * HID_ + col0 + ci;
                __nv_bfloat16 h16 = __float2bfloat16(yv);
                yh[yi] = h16;
                yl[yi] = __float2bfloat16(yv - __bfloat162float(h16));
            }
        }
    }
}

// ---------------- launch ---------------------------------------------------
extern "C" void kernel_launch(void* const* d_in, const int* in_sizes, int n_in,
                              void* d_out, int out_size)
{
    const float* x      = (const float*)d_in[0];
    const float* norm_w = (const float*)d_in[1];
    const float* Wq     = (const float*)d_in[2];
    const float* Wk     = (const float*)d_in[3];
    const float* Wv     = (const float*)d_in[4];
    const float* Wbeta  = (const float*)d_in[5];
    const float* bbeta  = (const float*)d_in[6];
    const float* Wig    = (const float*)d_in[7];
    const float* big    = (const float*)d_in[8];
    const float* Wog    = (const float*)d_in[9];
    const float* bog    = (const float*)d_in[10];
    const float* Wout   = (const float*)d_in[11];
    const float* bout   = (const float*)d_in[12];
    float* out = (float*)d_out;

    float *hbuf, *qb, *kb, *vb, *gb, *rt;
    __nv_bfloat16 *hh, *hl, *yh, *yl, *wh, *wl;
    cudaGetSymbolAddress((void**)&hbuf, g_h);
    cudaGetSymbolAddress((void**)&hh,   g_hh);
    cudaGetSymbolAddress((void**)&hl,   g_hl);
    cudaGetSymbolAddress((void**)&qb,   g_q);
    cudaGetSymbolAddress((void**)&kb,   g_k);
    cudaGetSymbolAddress((void**)&vb,   g_v);
    cudaGetSymbolAddress((void**)&yh,   g_yh);
    cudaGetSymbolAddress((void**)&yl,   g_yl);
    cudaGetSymbolAddress((void**)&wh,   g_wh);
    cudaGetSymbolAddress((void**)&wl,   g_wl);
    cudaGetSymbolAddress((void**)&gb,   g_gates);
    cudaGetSymbolAddress((void**)&rt,   g_rope);

    cudaFuncSetAttribute(gemm_bf16x2, cudaFuncAttributeMaxDynamicSharedMemorySize, GSMEM);

    const size_t WSZ = (size_t)HID_ * HID_;
    const int n4 = (int)(WSZ / 4);
    dim3 ggrid(HID_ / 128, ROWS_ / 128);

    rmsnorm_kernel<<<ROWS_, 256>>>(x, norm_w, hbuf, hh, hl);                        // 0
    splitf_kernel<<<(n4 + 255) / 256, 256>>>(Wq,   wh,           wl,           n4); // 1
    splitf_kernel<<<(n4 + 255) / 256, 256>>>(Wk,   wh + WSZ,     wl + WSZ,     n4); // 2
    splitf_kernel<<<(n4 + 255) / 256, 256>>>(Wv,   wh + 2 * WSZ, wl + 2 * WSZ, n4); // 3

    gemm_bf16x2<<<ggrid, 256, GSMEM>>>(hh, hl, wh,           wl,           nullptr, qb, ROWS_, HID_, HID_); // 4
    gemm_bf16x2<<<ggrid, 256, GSMEM>>>(hh, hl, wh + WSZ,     wl + WSZ,     nullptr, kb, ROWS_, HID_, HID_); // 5
    gemm_bf16x2<<<ggrid, 256, GSMEM>>>(hh, hl, wh + 2 * WSZ, wl + 2 * WSZ, nullptr, vb, ROWS_, HID_, HID_); // 6

    splitf_kernel<<<(n4 + 255) / 256, 256>>>(Wout, wh + 3 * WSZ, wl + 3 * WSZ, n4);

    gates2_kernel<<<ROWS_ / 128, 128>>>(hbuf, Wbeta, bbeta, Wig, big, Wog, bog, gb);

    rope_table_kernel<<<(L_ * HALF_ + 255) / 256, 256>>>(rt);
    rope_apply_kernel<<<ROWS_, 512>>>(qb, kb, rt);

    recurrence2_kernel<<<dim3(8, B_ * NH_), 128>>>(qb, kb, vb, gb, yh, yl);

    gemm_bf16x2<<<ggrid, 256, GSMEM>>>(yh, yl, wh + 3 * WSZ, wl + 3 * WSZ, bout, out, ROWS_, HID_, HID_);
}

// round 8
// speedup vs baseline: 2.3700x; 1.0134x over previous
#include <cuda_runtime.h>
#include <cuda_bf16.h>
#include <math.h>
#include <stdint.h>

#define B_  4
#define L_  4096
#define HID_ 1024
#define NH_ 8
#define DH_ 128
#define HALF_ 64
#define ROWS_ (B_ * L_)          // 16384
#define SCALE_ 0.08838834764831845f  // 1/sqrt(128)

// ---------------- scratch (static device globals: allocation-free) ----------
__device__ float g_h[(size_t)ROWS_ * HID_];
__device__ __nv_bfloat16 g_hh[(size_t)ROWS_ * HID_];
__device__ __nv_bfloat16 g_hl[(size_t)ROWS_ * HID_];
__device__ float g_q[(size_t)ROWS_ * HID_];
__device__ float g_k[(size_t)ROWS_ * HID_];
__device__ float g_v[(size_t)ROWS_ * HID_];
__device__ __nv_bfloat16 g_yh[(size_t)ROWS_ * HID_];
__device__ __nv_bfloat16 g_yl[(size_t)ROWS_ * HID_];
__device__ __nv_bfloat16 g_wh[(size_t)4 * HID_ * HID_];
__device__ __nv_bfloat16 g_wl[(size_t)4 * HID_ * HID_];
__device__ float g_gates[3 * B_ * NH_ * L_];
__device__ float g_rope[2 * L_ * HALF_];

// ---------------- helpers -------------------------------------------------
__device__ __forceinline__ uint32_t s2u(const void* p) {
    return (uint32_t)__cvta_generic_to_shared(p);
}
__device__ __forceinline__ void cp16(uint32_t d, const void* p) {
    asm volatile("cp.async.cg.shared.global [%0],[%1],16;" :: "r"(d), "l"(p));
}
__device__ __forceinline__ void cp4(uint32_t d, const void* p) {
    asm volatile("cp.async.ca.shared.global [%0],[%1],4;" :: "r"(d), "l"(p));
}
__device__ __forceinline__ void cp_commit() {
    asm volatile("cp.async.commit_group;");
}
__device__ __forceinline__ void ldsm4(uint32_t* r, uint32_t a) {
    asm volatile("ldmatrix.sync.aligned.m8n8.x4.shared.b16 {%0,%1,%2,%3},[%4];"
                 : "=r"(r[0]), "=r"(r[1]), "=r"(r[2]), "=r"(r[3]) : "r"(a));
}
__device__ __forceinline__ void mma16816(float* c, const uint32_t* a, const uint32_t* b) {
    asm volatile("mma.sync.aligned.m16n8k16.row.col.f32.bf16.bf16.f32 "
                 "{%0,%1,%2,%3},{%4,%5,%6,%7},{%8,%9},{%0,%1,%2,%3};"
                 : "+f"(c[0]), "+f"(c[1]), "+f"(c[2]), "+f"(c[3])
                 : "r"(a[0]), "r"(a[1]), "r"(a[2]), "r"(a[3]), "r"(b[0]), "r"(b[1]));
}
__device__ __forceinline__ unsigned long long pk2(float a, float b) {
    unsigned long long r;
    asm("mov.b64 %0,{%1,%2};" : "=l"(r) : "r"(__float_as_uint(a)), "r"(__float_as_uint(b)));
    return r;
}
__device__ __forceinline__ unsigned long long mulx2(unsigned long long a, unsigned long long b) {
    unsigned long long r;
    asm("mul.rn.f32x2 %0,%1,%2;" : "=l"(r) : "l"(a), "l"(b));
    return r;
}
__device__ __forceinline__ unsigned long long fmax2(unsigned long long a, unsigned long long b, unsigned long long c) {
    unsigned long long r;
    asm("fma.rn.f32x2 %0,%1,%2,%3;" : "=l"(r) : "l"(a), "l"(b), "l"(c));
    return r;
}
__device__ __forceinline__ float upksum(unsigned long long v) {
    uint32_t lo, hi;
    asm("mov.b64 {%0,%1},%2;" : "=r"(lo), "=r"(hi) : "l"(v));
    return __uint_as_float(lo) + __uint_as_float(hi);
}
__device__ __forceinline__ void ldsv2(unsigned long long& a, unsigned long long& b, uint32_t addr) {
    asm volatile("ld.shared.v2.u64 {%0,%1},[%2];" : "=l"(a), "=l"(b) : "r"(addr));
}

// ---------------- RMSNorm (also emits bf16 hi/lo split) -------------------
__global__ __launch_bounds__(256) void rmsnorm_kernel(
    const float* __restrict__ x, const float* __restrict__ w, float* __restrict__ h,
    __nv_bfloat16* __restrict__ hh, __nv_bfloat16* __restrict__ hl)
{
    int row = blockIdx.x;
    int tid = threadIdx.x;
    const float4* xr = (const float4*)(x + (size_t)row * HID_);
    float4 xv = xr[tid];
    float ss = xv.x * xv.x + xv.y * xv.y + xv.z * xv.z + xv.w * xv.w;
    #pragma unroll
    for (int off = 16; off; off >>= 1) ss += __shfl_xor_sync(0xFFFFFFFFu, ss, off);
    __shared__ float red[8];
    __shared__ float rtot;
    int lane = tid & 31, warp = tid >> 5;
    if (lane == 0) red[warp] = ss;
    __syncthreads();
    if (tid == 0) {
        float s = 0.f;
        #pragma unroll
        for (int i = 0; i < 8; i++) s += red[i];
        rtot = rsqrtf(s * (1.0f / HID_) + 1e-6f);
    }
    __syncthreads();
    float r = rtot;
    const float4* wr = (const float4*)w;
    float4 wv = wr[tid];
    float o[4];
    o[0] = xv.x * r * wv.x; o[1] = xv.y * r * wv.y;
    o[2] = xv.z * r * wv.z; o[3] = xv.w * r * wv.w;
    ((float4*)(h + (size_t)row * HID_))[tid] = *(float4*)o;
    __nv_bfloat16 hi[4], lo[4];
    #pragma unroll
    for (int i = 0; i < 4; i++) {
        hi[i] = __float2bfloat16(o[i]);
        lo[i] = __float2bfloat16(o[i] - __bfloat162float(hi[i]));
    }
    size_t base = (size_t)row * HID_;
    ((__nv_bfloat162*)(hh + base))[tid * 2]     = __halves2bfloat162(hi[0], hi[1]);
    ((__nv_bfloat162*)(hh + base))[tid * 2 + 1] = __halves2bfloat162(hi[2], hi[3]);
    ((__nv_bfloat162*)(hl + base))[tid * 2]     = __halves2bfloat162(lo[0], lo[1]);
    ((__nv_bfloat162*)(hl + base))[tid * 2 + 1] = __halves2bfloat162(lo[2], lo[3]);
}

// ---------------- fp32 -> bf16 hi/lo split (weights) -----------------------
__global__ __launch_bounds__(256) void splitf_kernel(
    const float* __restrict__ s, __nv_bfloat16* __restrict__ hi,
    __nv_bfloat16* __restrict__ lo, int n4)
{
    int i = blockIdx.x * blockDim.x + threadIdx.x;
    if (i >= n4) return;
    float4 x = ((const float4*)s)[i];
    float v[4] = {x.x, x.y, x.z, x.w};
    __nv_bfloat16 h[4], l[4];
    #pragma unroll
    for (int j = 0; j < 4; j++) {
        h[j] = __float2bfloat16(v[j]);
        l[j] = __float2bfloat16(v[j] - __bfloat162float(h[j]));
    }
    ((__nv_bfloat162*)hi)[i * 2]     = __halves2bfloat162(h[0], h[1]);
    ((__nv_bfloat162*)hi)[i * 2 + 1] = __halves2bfloat162(h[2], h[3]);
    ((__nv_bfloat162*)lo)[i * 2]     = __halves2bfloat162(l[0], l[1]);
    ((__nv_bfloat162*)lo)[i * 2 + 1] = __halves2bfloat162(l[2], l[3]);
}

// ---------------- bf16-split GEMM: C = A * W^T (+bias), fp32 out ----------
// 2-stage cp.async pipeline, 2 CTAs/SM. Block 128x128x32, 8 warps, warp 32x64.
// 3-product compensation: Ah*Bh + Ah*Bl + Al*Bh.
#define GTILE 5120               // 128 * 40 bf16 elems per tile
#define GSTAGEB (4 * GTILE * 2)  // bytes per stage (Ah,Al,Bh,Bl) = 40960
#define GNST 2
#define GSMEM (GNST * GSTAGEB)   // 81920 bytes

__global__ __launch_bounds__(256, 2) void gemm_bf16x2(
    const __nv_bfloat16* __restrict__ Ah, const __nv_bfloat16* __restrict__ Al,
    const __nv_bfloat16* __restrict__ Bh, const __nv_bfloat16* __restrict__ Bl,
    const float* __restrict__ bias, float* __restrict__ C,
    int M, int N, int K)
{
    extern __shared__ __nv_bfloat16 sm[];
    uint32_t sbase = s2u(sm);
    int tid = threadIdx.x;
    int bm = blockIdx.y, bn = blockIdx.x;
    int w = tid >> 5, lane = tid & 31;
    int wm = (w & 3) * 32, wn = (w >> 2) * 64;
    int g = lane >> 2, tq = lane & 3;

    const __nv_bfloat16* srcs[4];
    srcs[0] = Ah + (size_t)(bm * 128) * K;
    srcs[1] = Al + (size_t)(bm * 128) * K;
    srcs[2] = Bh + (size_t)(bn * 128) * K;
    srcs[3] = Bl + (size_t)(bn * 128) * K;

    float acc[2][8][4];
    #pragma unroll
    for (int i = 0; i < 2; i++)
        #pragma unroll
        for (int j = 0; j < 8; j++)
            #pragma unroll
            for (int q = 0; q < 4; q++) acc[i][j][q] = 0.f;

    int rA = (lane & 7) + ((lane & 8) ? 8 : 0);
    int cA = (lane & 16) ? 8 : 0;
    int rB = (lane & 7) + ((lane & 16) ? 8 : 0);
    int cB = (lane & 8) ? 8 : 0;

    auto loadStage = [&](int st, int k0) {
        #pragma unroll
        for (int mtx = 0; mtx < 4; mtx++) {
            uint32_t dbase = sbase + st * GSTAGEB + mtx * (GTILE * 2);
            const __nv_bfloat16* s = srcs[mtx] + k0;
            #pragma unroll
            for (int rep = 0; rep < 2; rep++) {
                int j = tid + rep * 256;
                int row = j >> 2, cc = j & 3;
                cp16(dbase + row * 80 + cc * 16, s + (size_t)row * K + cc * 8);
            }
        }
    };

    loadStage(0, 0); cp_commit();

    int niter = K / 32;
    for (int it = 0; it < niter; it++) {
        int cur = it & 1;
        if (it + 1 < niter) {
            loadStage((it + 1) & 1, (it + 1) * 32); cp_commit();
            asm volatile("cp.async.wait_group 1;");
        } else {
            asm volatile("cp.async.wait_group 0;");
        }
        __syncthreads();

        uint32_t stb = sbase + cur * GSTAGEB;
        #pragma unroll
        for (int ks = 0; ks < 2; ks++) {
            int kb = ks * 16;
            uint32_t a_h[2][4], a_l[2][4];
            #pragma unroll
            for (int mi = 0; mi < 2; mi++) {
                uint32_t ad = stb + ((wm + mi * 16 + rA) * 40 + kb + cA) * 2;
                ldsm4(a_h[mi], ad);
                ldsm4(a_l[mi], ad + GTILE * 2);
            }
            #pragma unroll
            for (int np = 0; np < 4; np++) {
                uint32_t bd = stb + 2 * GTILE * 2 + ((wn + np * 16 + rB) * 40 + kb + cB) * 2;
                uint32_t b_h[4], b_l[4];
                ldsm4(b_h, bd);
                ldsm4(b_l, bd + GTILE * 2);
                #pragma unroll
                for (int mi = 0; mi < 2; mi++) {
                    mma16816(acc[mi][np * 2],     a_h[mi], b_h);
                    mma16816(acc[mi][np * 2 + 1], a_h[mi], b_h + 2);
                    mma16816(acc[mi][np * 2],     a_h[mi], b_l);
                    mma16816(acc[mi][np * 2 + 1], a_h[mi], b_l + 2);
                    mma16816(acc[mi][np * 2],     a_l[mi], b_h);
                    mma16816(acc[mi][np * 2 + 1], a_l[mi], b_h + 2);
                }
            }
        }
        __syncthreads();   // all warps done reading 'cur' before it is overwritten
    }

    int rowb = bm * 128 + wm;
    int colb = bn * 128 + wn;
    #pragma unroll
    for (int mi = 0; mi < 2; mi++) {
        int r0 = rowb + mi * 16 + g;
        #pragma unroll
        for (int nj = 0; nj < 8; nj++) {
            int cc = colb + nj * 8 + tq * 2;
            float bx = 0.f, by = 0.f;
            if (bias) { float2 b2 = *(const float2*)(bias + cc); bx = b2.x; by = b2.y; }
            float2 o0, o1;
            o0.x = acc[mi][nj][0] + bx; o0.y = acc[mi][nj][1] + by;
            o1.x = acc[mi][nj][2] + bx; o1.y = acc[mi][nj][3] + by;
            *(float2*)(C + (size_t)r0 * N + cc) = o0;
            *(float2*)(C + (size_t)(r0 + 8) * N + cc) = o1;
        }
    }
}

// ---------------- Gates as tiled mini-GEMM: 128 rows x 24 outputs ----------
__global__ __launch_bounds__(128) void gates2_kernel(
    const float* __restrict__ h,
    const float* __restrict__ Wb, const float* __restrict__ bb,
    const float* __restrict__ Wi, const float* __restrict__ bi,
    const float* __restrict__ Wo, const float* __restrict__ bo,
    float* __restrict__ gates)
{
    __shared__ float hs[128 * 65];
    __shared__ float ws[24 * 64];
    int tid = threadIdx.x;
    int r0 = blockIdx.x * 128;

    float acc[24];
    #pragma unroll
    for (int c = 0; c < 24; c++) acc[c] = 0.f;

    for (int k0 = 0; k0 < HID_; k0 += 64) {
        #pragma unroll
        for (int i = 0; i < 16; i++) {
            int idx = tid + i * 128;
            int row = idx >> 4, c4 = idx & 15;
            float4 v = *(const float4*)(h + (size_t)(r0 + row) * HID_ + k0 + c4 * 4);
            float* d = &hs[row * 65 + c4 * 4];
            d[0] = v.x; d[1] = v.y; d[2] = v.z; d[3] = v.w;
        }
        #pragma unroll
        for (int i = 0; i < 3; i++) {
            int idx = tid + i * 128;
            int c = idx >> 4, j4 = idx & 15;
            const float* src = (c < 8 ? Wb + c * HID_
                               : c < 16 ? Wi + (c - 8) * HID_
                                        : Wo + (c - 16) * HID_);
            float4 v = *(const float4*)(src + k0 + j4 * 4);
            float* d = &ws[c * 64 + j4 * 4];
            d[0] = v.x; d[1] = v.y; d[2] = v.z; d[3] = v.w;
        }
        __syncthreads();
        #pragma unroll 4
        for (int j = 0; j < 64; j++) {
            float hj = hs[tid * 65 + j];
            #pragma unroll
            for (int c = 0; c < 24; c++) acc[c] += hj * ws[c * 64 + j];
        }
        __syncthreads();
    }

    int row = r0 + tid;
    int b = row >> 12, t = row & 4095;
    #pragma unroll
    for (int gt = 0; gt < 3; gt++) {
        const float* bias = (gt == 0 ? bb : gt == 1 ? bi : bo);
        #pragma unroll
        for (int hd = 0; hd < 8; hd++) {
            float val = 1.f / (1.f + expf(-(acc[gt * 8 + hd] + bias[hd])));
            gates[(size_t)gt * (B_ * NH_ * L_) + (size_t)(b * NH_ + hd) * L_ + t] = val;
        }
    }
}

// ---------------- RoPE tables ---------------------------------------------
__global__ void rope_table_kernel(float* __restrict__ tab)
{
    int idx = blockIdx.x * blockDim.x + threadIdx.x;
    if (idx >= L_ * HALF_) return;
    int t = idx >> 6, j = idx & 63;
    double invf = exp(-(double)j / 64.0 * 9.210340371976182736);
    float ang = (float)t * (float)invf;
    tab[idx] = (float)cos((double)ang);
    tab[L_ * HALF_ + idx] = (float)sin((double)ang);
}

// ---------------- RoPE apply ----------------------------------------------
__global__ __launch_bounds__(512) void rope_apply_kernel(
    float* __restrict__ q, float* __restrict__ k, const float* __restrict__ tab)
{
    int row = blockIdx.x;
    int t = row % L_;
    int tid = threadIdx.x;
    int hh = tid >> 6, j = tid & 63;
    size_t base = (size_t)row * HID_ + hh * DH_;
    float c = tab[t * HALF_ + j];
    float s = tab[L_ * HALF_ + t * HALF_ + j];
    float q1 = q[base + j], q2 = q[base + HALF_ + j];
    q[base + j]          = q1 * c - q2 * s;
    q[base + HALF_ + j]  = q1 * s + q2 * c;
    float k1 = k[base + j], k2 = k[base + HALF_ + j];
    k[base + j]          = k1 * c - k2 * s;
    k[base + HALF_ + j]  = k1 * s + k2 * c;
}

// ---------------- Recurrence: group-synchronous (8 steps per barrier) ------
// 16 stages in two 8-step halves. One wait+2 barriers per 8 steps; compute
// steps run back-to-back so LDS latency pipelines across steps.
#define NSTG 16
#define STGF 340       // floats per stage: q 8x20, k 8x20, v 16, fgo 4
#define NGRP (L_ / 8)  // 512
__global__ __launch_bounds__(128) void recurrence3_kernel(
    const float* __restrict__ q, const float* __restrict__ k,
    const float* __restrict__ v, const float* __restrict__ gates,
    __nv_bfloat16* __restrict__ yh, __nv_bfloat16* __restrict__ yl)
{
    __shared__ float rs[NSTG * STGF];
    __shared__ __align__(16) float pp[16 * 128];
    __shared__ float ow[16];
    int split = blockIdx.x, bh = blockIdx.y;
    int b = bh >> 3, hh = bh & 7;
    int tid = threadIdx.x;
    int c = tid >> 3, rg = tid & 7;
    int col0 = split * 16;
    size_t headbase = (size_t)b * L_ * HID_ + hh * DH_;
    const float* fp = gates + (size_t)bh * L_;
    const float* gp = fp + (size_t)(B_ * NH_) * L_;
    const float* op = gp + (size_t)(B_ * NH_) * L_;
    uint32_t sb = s2u(rs);

    auto issue = [&](int t) {
        uint32_t base = sb + (t & (NSTG - 1)) * (STGF * 4);
        size_t row = headbase + (size_t)t * HID_;
        if (tid < 32) {
            cp16(base + (tid >> 2) * 80 + (tid & 3) * 16, q + row + tid * 4);
        } else if (tid < 64) {
            int j = tid - 32;
            cp16(base + 640 + (j >> 2) * 80 + (j & 3) * 16, k + row + j * 4);
        } else if (tid < 68) {
            int j = tid - 64;
            cp16(base + 1280 + j * 16, v + row + col0 + j * 4);
        } else if (tid < 71) {
            int j = tid - 68;
            const float* p = (j == 0 ? fp : (j == 1 ? gp : op)) + t;
            cp4(base + 1344 + j * 4, p);
        }
    };
    auto issueGroup = [&](int g) {
        if (g < NGRP) {
            int tb = g * 8;
            #pragma unroll
            for (int s = 0; s < 8; s++) issue(tb + s);
        }
        cp_commit();
    };

    issueGroup(0);
    issueGroup(1);

    unsigned long long M2[8];
    #pragma unroll
    for (int i = 0; i < 8; i++) M2[i] = 0ull;

    for (int g = 0; g < NGRP; g++) {
        asm volatile("cp.async.wait_group 1;");
        __syncthreads();                    // group g data visible to all
        int half = (g & 1) * 8;
        #pragma unroll
        for (int s = 0; s < 8; s++) {
            int t = g * 8 + s;
            uint32_t stb = sb + (half + s) * (STGF * 4);
            float ff = rs[(half + s) * STGF + 336];
            float gg = rs[(half + s) * STGF + 337];
            float vv = rs[(half + s) * STGF + 320 + c];
            if (tid == 0) ow[t & 15] = rs[(half + s) * STGF + 338];
            float c1 = gg * SCALE_ * vv;
            unsigned long long ffp = pk2(ff, ff);
            unsigned long long c1p = pk2(c1, c1);
            unsigned long long p2 = 0ull;
            uint32_t qa = stb + rg * 80;
            uint32_t ka = qa + 640;
            #pragma unroll
            for (int i = 0; i < 4; i++) {
                unsigned long long k0, k1, q0, q1, t0;
                ldsv2(k0, k1, ka + i * 16);
                ldsv2(q0, q1, qa + i * 16);
                t0 = mulx2(c1p, k0);
                M2[2 * i] = fmax2(M2[2 * i], ffp, t0);
                p2 = fmax2(q0, M2[2 * i], p2);
                t0 = mulx2(c1p, k1);
                M2[2 * i + 1] = fmax2(M2[2 * i + 1], ffp, t0);
                p2 = fmax2(q1, M2[2 * i + 1], p2);
            }
            pp[(t & 15) * 128 + c * 8 + rg] = upksum(p2);
        }
        __syncthreads();                    // done reading half + pp complete
        issueGroup(g + 2);                  // overwrite-safe now
        if (g & 1) {
            int t0i = (g - 1) * 8;
            #pragma unroll
            for (int r2 = 0; r2 < 2; r2++) {
                int oidx = tid + r2 * 128;
                int tt = oidx >> 4, ci = oidx & 15;
                float4 va = *(float4*)&pp[tt * 128 + ci * 8];
                float4 vb = *(float4*)&pp[tt * 128 + ci * 8 + 4];
                float s = ((va.x + va.y) + (va.z + va.w)) + ((vb.x + vb.y) + (vb.z + vb.w));
                float yv = ow[tt] * s;
                size_t yi = headbase + (size_t)(t0i + tt) * HID_ + col0 + ci;
                __nv_bfloat16 h16 = __float2bfloat16(yv);
                yh[yi] = h16;
                yl[yi] = __float2bfloat16(yv - __bfloat162float(h16));
            }
        }
    }
}

// ---------------- launch ---------------------------------------------------
extern "C" void kernel_launch(void* const* d_in, const int* in_sizes, int n_in,
                              void* d_out, int out_size)
{
    const float* x      = (const float*)d_in[0];
    const float* norm_w = (const float*)d_in[1];
    const float* Wq     = (const float*)d_in[2];
    const float* Wk     = (const float*)d_in[3];
    const float* Wv     = (const float*)d_in[4];
    const float* Wbeta  = (const float*)d_in[5];
    const float* bbeta  = (const float*)d_in[6];
    const float* Wig    = (const float*)d_in[7];
    const float* big    = (const float*)d_in[8];
    const float* Wog    = (const float*)d_in[9];
    const float* bog    = (const float*)d_in[10];
    const float* Wout   = (const float*)d_in[11];
    const float* bout   = (const float*)d_in[12];
    float* out = (float*)d_out;

    float *hbuf, *qb, *kb, *vb, *gb, *rt;
    __nv_bfloat16 *hh, *hl, *yh, *yl, *wh, *wl;
    cudaGetSymbolAddress((void**)&hbuf, g_h);
    cudaGetSymbolAddress((void**)&hh,   g_hh);
    cudaGetSymbolAddress((void**)&hl,   g_hl);
    cudaGetSymbolAddress((void**)&qb,   g_q);
    cudaGetSymbolAddress((void**)&kb,   g_k);
    cudaGetSymbolAddress((void**)&vb,   g_v);
    cudaGetSymbolAddress((void**)&yh,   g_yh);
    cudaGetSymbolAddress((void**)&yl,   g_yl);
    cudaGetSymbolAddress((void**)&wh,   g_wh);
    cudaGetSymbolAddress((void**)&wl,   g_wl);
    cudaGetSymbolAddress((void**)&gb,   g_gates);
    cudaGetSymbolAddress((void**)&rt,   g_rope);

    cudaFuncSetAttribute(gemm_bf16x2, cudaFuncAttributeMaxDynamicSharedMemorySize, GSMEM);

    const size_t WSZ = (size_t)HID_ * HID_;
    const int n4 = (int)(WSZ / 4);
    dim3 ggrid(HID_ / 128, ROWS_ / 128);

    rmsnorm_kernel<<<ROWS_, 256>>>(x, norm_w, hbuf, hh, hl);                        // 0
    splitf_kernel<<<(n4 + 255) / 256, 256>>>(Wq,   wh,           wl,           n4); // 1
    splitf_kernel<<<(n4 + 255) / 256, 256>>>(Wk,   wh + WSZ,     wl + WSZ,     n4); // 2
    gemm_bf16x2<<<ggrid, 256, GSMEM>>>(hh, hl, wh, wl, nullptr, qb, ROWS_, HID_, HID_); // 3 (profiled)
    splitf_kernel<<<(n4 + 255) / 256, 256>>>(Wv,   wh + 2 * WSZ, wl + 2 * WSZ, n4); // 4
    gemm_bf16x2<<<ggrid, 256, GSMEM>>>(hh, hl, wh + WSZ,     wl + WSZ,     nullptr, kb, ROWS_, HID_, HID_); // 5
    gemm_bf16x2<<<ggrid, 256, GSMEM>>>(hh, hl, wh + 2 * WSZ, wl + 2 * WSZ, nullptr, vb, ROWS_, HID_, HID_); // 6

    splitf_kernel<<<(n4 + 255) / 256, 256>>>(Wout, wh + 3 * WSZ, wl + 3 * WSZ, n4);

    gates2_kernel<<<ROWS_ / 128, 128>>>(hbuf, Wbeta, bbeta, Wig, big, Wog, bog, gb);

    rope_table_kernel<<<(L_ * HALF_ + 255) / 256, 256>>>(rt);
    rope_apply_kernel<<<ROWS_, 512>>>(qb, kb, rt);

    recurrence3_kernel<<<dim3(8, B_ * NH_), 128>>>(qb, kb, vb, gb, yh, yl);

    gemm_bf16x2<<<ggrid, 256, GSMEM>>>(yh, yl, wh + 3 * WSZ, wl + 3 * WSZ, bout, out, ROWS_, HID_, HID_);
}

// round 9
// speedup vs baseline: 2.8673x; 1.2098x over previous
#include <cuda_runtime.h>
#include <cuda_fp16.h>
#include <cuda_bf16.h>
#include <math.h>
#include <stdint.h>

#define B_  4
#define L_  4096
#define HID_ 1024
#define NH_ 8
#define DH_ 128
#define HALF_ 64
#define ROWS_ (B_ * L_)          // 16384
#define SCALE_ 0.08838834764831845f  // 1/sqrt(128)

// ---------------- scratch (static device globals: allocation-free) ----------
__device__ float g_h[(size_t)ROWS_ * HID_];
__device__ __half g_hf[(size_t)ROWS_ * HID_];
__device__ float g_q[(size_t)ROWS_ * HID_];
__device__ float g_k[(size_t)ROWS_ * HID_];
__device__ float g_v[(size_t)ROWS_ * HID_];
__device__ __half g_yf[(size_t)ROWS_ * HID_];
__device__ __half g_wh[(size_t)4 * HID_ * HID_];
__device__ __half g_wl[(size_t)4 * HID_ * HID_];
__device__ float g_gates[3 * B_ * NH_ * L_];
__device__ float g_rope[2 * L_ * HALF_];

// ---------------- helpers -------------------------------------------------
__device__ __forceinline__ uint32_t s2u(const void* p) {
    return (uint32_t)__cvta_generic_to_shared(p);
}
__device__ __forceinline__ void cp16(uint32_t d, const void* p) {
    asm volatile("cp.async.cg.shared.global [%0],[%1],16;" :: "r"(d), "l"(p));
}
__device__ __forceinline__ void cp4(uint32_t d, const void* p) {
    asm volatile("cp.async.ca.shared.global [%0],[%1],4;" :: "r"(d), "l"(p));
}
__device__ __forceinline__ void cp_commit() {
    asm volatile("cp.async.commit_group;");
}
__device__ __forceinline__ void ldsm4(uint32_t* r, uint32_t a) {
    asm volatile("ldmatrix.sync.aligned.m8n8.x4.shared.b16 {%0,%1,%2,%3},[%4];"
                 : "=r"(r[0]), "=r"(r[1]), "=r"(r[2]), "=r"(r[3]) : "r"(a));
}
__device__ __forceinline__ void mma16816h(float* c, const uint32_t* a, const uint32_t* b) {
    asm volatile("mma.sync.aligned.m16n8k16.row.col.f32.f16.f16.f32 "
                 "{%0,%1,%2,%3},{%4,%5,%6,%7},{%8,%9},{%0,%1,%2,%3};"
                 : "+f"(c[0]), "+f"(c[1]), "+f"(c[2]), "+f"(c[3])
                 : "r"(a[0]), "r"(a[1]), "r"(a[2]), "r"(a[3]), "r"(b[0]), "r"(b[1]));
}
__device__ __forceinline__ unsigned long long pk2(float a, float b) {
    unsigned long long r;
    asm("mov.b64 %0,{%1,%2};" : "=l"(r) : "r"(__float_as_uint(a)), "r"(__float_as_uint(b)));
    return r;
}
__device__ __forceinline__ unsigned long long mulx2(unsigned long long a, unsigned long long b) {
    unsigned long long r;
    asm("mul.rn.f32x2 %0,%1,%2;" : "=l"(r) : "l"(a), "l"(b));
    return r;
}
__device__ __forceinline__ unsigned long long fmax2(unsigned long long a, unsigned long long b, unsigned long long c) {
    unsigned long long r;
    asm("fma.rn.f32x2 %0,%1,%2,%3;" : "=l"(r) : "l"(a), "l"(b), "l"(c));
    return r;
}
__device__ __forceinline__ float upksum(unsigned long long v) {
    uint32_t lo, hi;
    asm("mov.b64 {%0,%1},%2;" : "=r"(lo), "=r"(hi) : "l"(v));
    return __uint_as_float(lo) + __uint_as_float(hi);
}
__device__ __forceinline__ void ldsv2(unsigned long long& a, unsigned long long& b, uint32_t addr) {
    asm volatile("ld.shared.v2.u64 {%0,%1},[%2];" : "=l"(a), "=l"(b) : "r"(addr));
}

// ---------------- RMSNorm (emits fp32 h + single fp16 hf) ------------------
__global__ __launch_bounds__(256) void rmsnorm_kernel(
    const float* __restrict__ x, const float* __restrict__ w, float* __restrict__ h,
    __half* __restrict__ hf)
{
    int row = blockIdx.x;
    int tid = threadIdx.x;
    const float4* xr = (const float4*)(x + (size_t)row * HID_);
    float4 xv = xr[tid];
    float ss = xv.x * xv.x + xv.y * xv.y + xv.z * xv.z + xv.w * xv.w;
    #pragma unroll
    for (int off = 16; off; off >>= 1) ss += __shfl_xor_sync(0xFFFFFFFFu, ss, off);
    __shared__ float red[8];
    __shared__ float rtot;
    int lane = tid & 31, warp = tid >> 5;
    if (lane == 0) red[warp] = ss;
    __syncthreads();
    if (tid == 0) {
        float s = 0.f;
        #pragma unroll
        for (int i = 0; i < 8; i++) s += red[i];
        rtot = rsqrtf(s * (1.0f / HID_) + 1e-6f);
    }
    __syncthreads();
    float r = rtot;
    const float4* wr = (const float4*)w;
    float4 wv = wr[tid];
    float o[4];
    o[0] = xv.x * r * wv.x; o[1] = xv.y * r * wv.y;
    o[2] = xv.z * r * wv.z; o[3] = xv.w * r * wv.w;
    ((float4*)(h + (size_t)row * HID_))[tid] = *(float4*)o;
    size_t base = (size_t)row * HID_;
    ((__half2*)(hf + base))[tid * 2]     = __halves2half2(__float2half(o[0]), __float2half(o[1]));
    ((__half2*)(hf + base))[tid * 2 + 1] = __halves2half2(__float2half(o[2]), __float2half(o[3]));
}

// ---------------- fp32 -> fp16 hi/lo split (weights) -----------------------
__global__ __launch_bounds__(256) void splitf_kernel(
    const float* __restrict__ s, __half* __restrict__ hi,
    __half* __restrict__ lo, int n4)
{
    int i = blockIdx.x * blockDim.x + threadIdx.x;
    if (i >= n4) return;
    float4 x = ((const float4*)s)[i];
    float v[4] = {x.x, x.y, x.z, x.w};
    __half h[4], l[4];
    #pragma unroll
    for (int j = 0; j < 4; j++) {
        h[j] = __float2half(v[j]);
        l[j] = __float2half(v[j] - __half2float(h[j]));
    }
    ((__half2*)hi)[i * 2]     = __halves2half2(h[0], h[1]);
    ((__half2*)hi)[i * 2 + 1] = __halves2half2(h[2], h[3]);
    ((__half2*)lo)[i * 2]     = __halves2half2(l[0], l[1]);
    ((__half2*)lo)[i * 2 + 1] = __halves2half2(l[2], l[3]);
}

// ---------------- fp16 2-product GEMM: C = A * W^T (+bias), fp32 out ------
// A single fp16, W split hi/lo. P = A*Wh + A*Wl. 3-stage cp.async, 2 CTAs/SM.
#define GTILE 5120               // 128 * 40 halves per tile
#define GSTAGEB (3 * GTILE * 2)  // bytes per stage (A, Bh, Bl) = 30720
#define GNST 3
#define GSMEM (GNST * GSTAGEB)   // 92160

__global__ __launch_bounds__(256, 2) void gemm_h2(
    const __half* __restrict__ A, const __half* __restrict__ Bh,
    const __half* __restrict__ Bl,
    const float* __restrict__ bias, float* __restrict__ C,
    int M, int N, int K)
{
    extern __shared__ __half sm[];
    uint32_t sbase = s2u(sm);
    int tid = threadIdx.x;
    int bm = blockIdx.y, bn = blockIdx.x;
    int w = tid >> 5, lane = tid & 31;
    int wm = (w & 3) * 32, wn = (w >> 2) * 64;
    int g = lane >> 2, tq = lane & 3;

    const __half* srcs[3];
    srcs[0] = A  + (size_t)(bm * 128) * K;
    srcs[1] = Bh + (size_t)(bn * 128) * K;
    srcs[2] = Bl + (size_t)(bn * 128) * K;

    float acc[2][8][4];
    #pragma unroll
    for (int i = 0; i < 2; i++)
        #pragma unroll
        for (int j = 0; j < 8; j++)
            #pragma unroll
            for (int q = 0; q < 4; q++) acc[i][j][q] = 0.f;

    int rA = (lane & 7) + ((lane & 8) ? 8 : 0);
    int cA = (lane & 16) ? 8 : 0;
    int rB = (lane & 7) + ((lane & 16) ? 8 : 0);
    int cB = (lane & 8) ? 8 : 0;

    auto loadStage = [&](int st, int k0) {
        #pragma unroll
        for (int mtx = 0; mtx < 3; mtx++) {
            uint32_t dbase = sbase + st * GSTAGEB + mtx * (GTILE * 2);
            const __half* s = srcs[mtx] + k0;
            #pragma unroll
            for (int rep = 0; rep < 2; rep++) {
                int j = tid + rep * 256;
                int row = j >> 2, cc = j & 3;
                cp16(dbase + row * 80 + cc * 16, s + (size_t)row * K + cc * 8);
            }
        }
    };

    loadStage(0, 0);  cp_commit();
    loadStage(1, 32); cp_commit();

    int niter = K / 32;
    for (int it = 0; it < niter; it++) {
        if (it == niter - 1) asm volatile("cp.async.wait_group 0;");
        else                 asm volatile("cp.async.wait_group 1;");
        __syncthreads();
        int cur = it % GNST;
        uint32_t stb = sbase + cur * GSTAGEB;
        #pragma unroll
        for (int ks = 0; ks < 2; ks++) {
            int kb = ks * 16;
            uint32_t a_f[2][4];
            #pragma unroll
            for (int mi = 0; mi < 2; mi++) {
                uint32_t ad = stb + ((wm + mi * 16 + rA) * 40 + kb + cA) * 2;
                ldsm4(a_f[mi], ad);
            }
            #pragma unroll
            for (int np = 0; np < 4; np++) {
                uint32_t bd = stb + GTILE * 2 + ((wn + np * 16 + rB) * 40 + kb + cB) * 2;
                uint32_t b_h[4], b_l[4];
                ldsm4(b_h, bd);
                ldsm4(b_l, bd + GTILE * 2);
                #pragma unroll
                for (int mi = 0; mi < 2; mi++) {
                    mma16816h(acc[mi][np * 2],     a_f[mi], b_h);
                    mma16816h(acc[mi][np * 2 + 1], a_f[mi], b_h + 2);
                    mma16816h(acc[mi][np * 2],     a_f[mi], b_l);
                    mma16816h(acc[mi][np * 2 + 1], a_f[mi], b_l + 2);
                }
            }
        }
        if (it + 2 < niter) { loadStage((it + 2) % GNST, (it + 2) * 32); cp_commit(); }
    }

    int rowb = bm * 128 + wm;
    int colb = bn * 128 + wn;
    #pragma unroll
    for (int mi = 0; mi < 2; mi++) {
        int r0 = rowb + mi * 16 + g;
        #pragma unroll
        for (int nj = 0; nj < 8; nj++) {
            int cc = colb + nj * 8 + tq * 2;
            float bx = 0.f, by = 0.f;
            if (bias) { float2 b2 = *(const float2*)(bias + cc); bx = b2.x; by = b2.y; }
            float2 o0, o1;
            o0.x = acc[mi][nj][0] + bx; o0.y = acc[mi][nj][1] + by;
            o1.x = acc[mi][nj][2] + bx; o1.y = acc[mi][nj][3] + by;
            *(float2*)(C + (size_t)r0 * N + cc) = o0;
            *(float2*)(C + (size_t)(r0 + 8) * N + cc) = o1;
        }
    }
}

// ---------------- Gates as tiled mini-GEMM: 128 rows x 24 outputs ----------
__global__ __launch_bounds__(128) void gates2_kernel(
    const float* __restrict__ h,
    const float* __restrict__ Wb, const float* __restrict__ bb,
    const float* __restrict__ Wi, const float* __restrict__ bi,
    const float* __restrict__ Wo, const float* __restrict__ bo,
    float* __restrict__ gates)
{
    __shared__ float hs[128 * 65];
    __shared__ float ws[24 * 64];
    int tid = threadIdx.x;
    int r0 = blockIdx.x * 128;

    float acc[24];
    #pragma unroll
    for (int c = 0; c < 24; c++) acc[c] = 0.f;

    for (int k0 = 0; k0 < HID_; k0 += 64) {
        #pragma unroll
        for (int i = 0; i < 16; i++) {
            int idx = tid + i * 128;
            int row = idx >> 4, c4 = idx & 15;
            float4 v = *(const float4*)(h + (size_t)(r0 + row) * HID_ + k0 + c4 * 4);
            float* d = &hs[row * 65 + c4 * 4];
            d[0] = v.x; d[1] = v.y; d[2] = v.z; d[3] = v.w;
        }
        #pragma unroll
        for (int i = 0; i < 3; i++) {
            int idx = tid + i * 128;
            int c = idx >> 4, j4 = idx & 15;
            const float* src = (c < 8 ? Wb + c * HID_
                               : c < 16 ? Wi + (c - 8) * HID_
                                        : Wo + (c - 16) * HID_);
            float4 v = *(const float4*)(src + k0 + j4 * 4);
            float* d = &ws[c * 64 + j4 * 4];
            d[0] = v.x; d[1] = v.y; d[2] = v.z; d[3] = v.w;
        }
        __syncthreads();
        #pragma unroll 4
        for (int j = 0; j < 64; j++) {
            float hj = hs[tid * 65 + j];
            #pragma unroll
            for (int c = 0; c < 24; c++) acc[c] += hj * ws[c * 64 + j];
        }
        __syncthreads();
    }

    int row = r0 + tid;
    int b = row >> 12, t = row & 4095;
    #pragma unroll
    for (int gt = 0; gt < 3; gt++) {
        const float* bias = (gt == 0 ? bb : gt == 1 ? bi : bo);
        #pragma unroll
        for (int hd = 0; hd < 8; hd++) {
            float val = 1.f / (1.f + expf(-(acc[gt * 8 + hd] + bias[hd])));
            gates[(size_t)gt * (B_ * NH_ * L_) + (size_t)(b * NH_ + hd) * L_ + t] = val;
        }
    }
}

// ---------------- RoPE tables ---------------------------------------------
__global__ void rope_table_kernel(float* __restrict__ tab)
{
    int idx = blockIdx.x * blockDim.x + threadIdx.x;
    if (idx >= L_ * HALF_) return;
    int t = idx >> 6, j = idx & 63;
    double invf = exp(-(double)j / 64.0 * 9.210340371976182736);
    float ang = (float)t * (float)invf;
    tab[idx] = (float)cos((double)ang);
    tab[L_ * HALF_ + idx] = (float)sin((double)ang);
}

// ---------------- RoPE apply ----------------------------------------------
__global__ __launch_bounds__(512) void rope_apply_kernel(
    float* __restrict__ q, float* __restrict__ k, const float* __restrict__ tab)
{
    int row = blockIdx.x;
    int t = row % L_;
    int tid = threadIdx.x;
    int hh = tid >> 6, j = tid & 63;
    size_t base = (size_t)row * HID_ + hh * DH_;
    float c = tab[t * HALF_ + j];
    float s = tab[L_ * HALF_ + t * HALF_ + j];
    float q1 = q[base + j], q2 = q[base + HALF_ + j];
    q[base + j]          = q1 * c - q2 * s;
    q[base + HALF_ + j]  = q1 * s + q2 * c;
    float k1 = k[base + j], k2 = k[base + HALF_ + j];
    k[base + j]          = k1 * c - k2 * s;
    k[base + HALF_ + j]  = k1 * s + k2 * c;
}

// ---------------- Recurrence: 6-group ring (48-step prefetch) --------------
#define RNG 6
#define STGF 340       // floats per stage: q 8x20, k 8x20, v 16, fgo 4
#define NGRP (L_ / 8)  // 512
#define RSMEM (RNG * 8 * STGF * 4)   // 65280 bytes dynamic

__global__ __launch_bounds__(128) void recurrence4_kernel(
    const float* __restrict__ q, const float* __restrict__ k,
    const float* __restrict__ v, const float* __restrict__ gates,
    __half* __restrict__ yf)
{
    extern __shared__ float rs[];
    __shared__ __align__(16) float pp[16 * 128];
    __shared__ float ow[16];
    int split = blockIdx.x, bh = blockIdx.y;
    int b = bh >> 3, hh = bh & 7;
    int tid = threadIdx.x;
    int c = tid >> 3, rg = tid & 7;
    int col0 = split * 16;
    size_t headbase = (size_t)b * L_ * HID_ + hh * DH_;
    const float* fp = gates + (size_t)bh * L_;
    const float* gp = fp + (size_t)(B_ * NH_) * L_;
    const float* op = gp + (size_t)(B_ * NH_) * L_;
    uint32_t sb = s2u(rs);

    auto issue = [&](int t, int st) {
        uint32_t base = sb + st * (STGF * 4);
        size_t row = headbase + (size_t)t * HID_;
        if (tid < 32) {
            cp16(base + (tid >> 2) * 80 + (tid & 3) * 16, q + row + tid * 4);
        } else if (tid < 64) {
            int j = tid - 32;
            cp16(base + 640 + (j >> 2) * 80 + (j & 3) * 16, k + row + j * 4);
        } else if (tid < 68) {
            int j = tid - 64;
            cp16(base + 1280 + j * 16, v + row + col0 + j * 4);
        } else if (tid < 71) {
            int j = tid - 68;
            const float* p = (j == 0 ? fp : (j == 1 ? gp : op)) + t;
            cp4(base + 1344 + j * 4, p);
        }
    };
    auto issueGroup = [&](int g) {
        if (g < NGRP) {
            int ring = (g % RNG) * 8;
            #pragma unroll
            for (int s = 0; s < 8; s++) issue(g * 8 + s, ring + s);
        }
        cp_commit();
    };

    #pragma unroll
    for (int g = 0; g < RNG; g++) issueGroup(g);

    unsigned long long M2[8];
    #pragma unroll
    for (int i = 0; i < 8; i++) M2[i] = 0ull;

    for (int g = 0; g < NGRP; g++) {
        asm volatile("cp.async.wait_group 5;");
        __syncthreads();                    // group g data visible to all
        int ring = (g % RNG) * 8;
        #pragma unroll
        for (int s = 0; s < 8; s++) {
            int t = g * 8 + s;
            int st = ring + s;
            uint32_t stb = sb + st * (STGF * 4);
            float ff = rs[st * STGF + 336];
            float gg = rs[st * STGF + 337];
            float vv = rs[st * STGF + 320 + c];
            if (tid == 0) ow[t & 15] = rs[st * STGF + 338];
            float c1 = gg * SCALE_ * vv;
            unsigned long long ffp = pk2(ff, ff);
            unsigned long long c1p = pk2(c1, c1);
            unsigned long long p2 = 0ull;
            uint32_t qa = stb + rg * 80;
            uint32_t ka = qa + 640;
            #pragma unroll
            for (int i = 0; i < 4; i++) {
                unsigned long long k0, k1, q0, q1, t0;
                ldsv2(k0, k1, ka + i * 16);
                ldsv2(q0, q1, qa + i * 16);
                t0 = mulx2(c1p, k0);
                M2[2 * i] = fmax2(M2[2 * i], ffp, t0);
                p2 = fmax2(q0, M2[2 * i], p2);
                t0 = mulx2(c1p, k1);
                M2[2 * i + 1] = fmax2(M2[2 * i + 1], ffp, t0);
                p2 = fmax2(q1, M2[2 * i + 1], p2);
            }
            pp[(t & 15) * 128 + c * 8 + rg] = upksum(p2);
        }
        __syncthreads();                    // done reading ring slot + pp complete
        issueGroup(g + RNG);                // overwrite-safe now
        if (g & 1) {
            int t0i = (g - 1) * 8;
            #pragma unroll
            for (int r2 = 0; r2 < 2; r2++) {
                int oidx = tid + r2 * 128;
                int tt = oidx >> 4, ci = oidx & 15;
                float4 va = *(float4*)&pp[tt * 128 + ci * 8];
                float4 vb = *(float4*)&pp[tt * 128 + ci * 8 + 4];
                float s = ((va.x + va.y) + (va.z + va.w)) + ((vb.x + vb.y) + (vb.z + vb.w));
                float yv = ow[tt] * s;
                size_t yi = headbase + (size_t)(t0i + tt) * HID_ + col0 + ci;
                yf[yi] = __float2half(yv);
            }
        }
    }
}

// ---------------- launch ---------------------------------------------------
extern "C" void kernel_launch(void* const* d_in, const int* in_sizes, int n_in,
                              void* d_out, int out_size)
{
    const float* x      = (const float*)d_in[0];
    const float* norm_w = (const float*)d_in[1];
    const float* Wq     = (const float*)d_in[2];
    const float* Wk     = (const float*)d_in[3];
    const float* Wv     = (const float*)d_in[4];
    const float* Wbeta  = (const float*)d_in[5];
    const float* bbeta  = (const float*)d_in[6];
    const float* Wig    = (const float*)d_in[7];
    const float* big    = (const float*)d_in[8];
    const float* Wog    = (const float*)d_in[9];
    const float* bog    = (const float*)d_in[10];
    const float* Wout   = (const float*)d_in[11];
    const float* bout   = (const float*)d_in[12];
    float* out = (float*)d_out;

    float *hbuf, *qb, *kb, *vb, *gb, *rt;
    __half *hf, *yf, *wh, *wl;
    cudaGetSymbolAddress((void**)&hbuf, g_h);
    cudaGetSymbolAddress((void**)&hf,   g_hf);
    cudaGetSymbolAddress((void**)&qb,   g_q);
    cudaGetSymbolAddress((void**)&kb,   g_k);
    cudaGetSymbolAddress((void**)&vb,   g_v);
    cudaGetSymbolAddress((void**)&yf,   g_yf);
    cudaGetSymbolAddress((void**)&wh,   g_wh);
    cudaGetSymbolAddress((void**)&wl,   g_wl);
    cudaGetSymbolAddress((void**)&gb,   g_gates);
    cudaGetSymbolAddress((void**)&rt,   g_rope);

    cudaFuncSetAttribute(gemm_h2, cudaFuncAttributeMaxDynamicSharedMemorySize, GSMEM);
    cudaFuncSetAttribute(recurrence4_kernel, cudaFuncAttributeMaxDynamicSharedMemorySize, RSMEM);

    const size_t WSZ = (size_t)HID_ * HID_;
    const int n4 = (int)(WSZ / 4);
    dim3 ggrid(HID_ / 128, ROWS_ / 128);

    rmsnorm_kernel<<<ROWS_, 256>>>(x, norm_w, hbuf, hf);                            // 0
    splitf_kernel<<<(n4 + 255) / 256, 256>>>(Wq,   wh,           wl,           n4); // 1
    splitf_kernel<<<(n4 + 255) / 256, 256>>>(Wk,   wh + WSZ,     wl + WSZ,     n4); // 2
    gemm_h2<<<ggrid, 256, GSMEM>>>(hf, wh, wl, nullptr, qb, ROWS_, HID_, HID_);     // 3 (profiled)
    splitf_kernel<<<(n4 + 255) / 256, 256>>>(Wv,   wh + 2 * WSZ, wl + 2 * WSZ, n4); // 4
    gemm_h2<<<ggrid, 256, GSMEM>>>(hf, wh + WSZ,     wl + WSZ,     nullptr, kb, ROWS_, HID_, HID_);
    gemm_h2<<<ggrid, 256, GSMEM>>>(hf, wh + 2 * WSZ, wl + 2 * WSZ, nullptr, vb, ROWS_, HID_, HID_);

    splitf_kernel<<<(n4 + 255) / 256, 256>>>(Wout, wh + 3 * WSZ, wl + 3 * WSZ, n4);

    gates2_kernel<<<ROWS_ / 128, 128>>>(hbuf, Wbeta, bbeta, Wig, big, Wog, bog, gb);

    rope_table_kernel<<<(L_ * HALF_ + 255) / 256, 256>>>(rt);
    rope_apply_kernel<<<ROWS_, 512>>>(qb, kb, rt);

    recurrence4_kernel<<<dim3(8, B_ * NH_), 128, RSMEM>>>(qb, kb, vb, gb, yf);

    gemm_h2<<<ggrid, 256, GSMEM>>>(yf, wh + 3 * WSZ, wl + 3 * WSZ, bout, out, ROWS_, HID_, HID_);
}

// round 10
// speedup vs baseline: 2.8897x; 1.0078x over previous
#include <cuda_runtime.h>
#include <cuda_fp16.h>
#include <cuda_bf16.h>
#include <math.h>
#include <stdint.h>

#define B_  4
#define L_  4096
#define HID_ 1024
#define NH_ 8
#define DH_ 128
#define HALF_ 64
#define ROWS_ (B_ * L_)          // 16384
#define SCALE_ 0.08838834764831845f  // 1/sqrt(128)

// ---------------- scratch (static device globals: allocation-free) ----------
__device__ float g_h[(size_t)ROWS_ * HID_];
__device__ __half g_hf[(size_t)ROWS_ * HID_];
__device__ float g_q[(size_t)ROWS_ * HID_];
__device__ float g_k[(size_t)ROWS_ * HID_];
__device__ float g_v[(size_t)ROWS_ * HID_];
__device__ __half g_yf[(size_t)ROWS_ * HID_];
__device__ __half g_wh[(size_t)4 * HID_ * HID_];
__device__ __half g_wl[(size_t)4 * HID_ * HID_];
__device__ float g_gates[3 * B_ * NH_ * L_];
__device__ float g_rope[2 * L_ * HALF_];

// ---------------- helpers -------------------------------------------------
__device__ __forceinline__ uint32_t s2u(const void* p) {
    return (uint32_t)__cvta_generic_to_shared(p);
}
__device__ __forceinline__ void cp16(uint32_t d, const void* p) {
    asm volatile("cp.async.cg.shared.global [%0],[%1],16;" :: "r"(d), "l"(p));
}
__device__ __forceinline__ void cp4(uint32_t d, const void* p) {
    asm volatile("cp.async.ca.shared.global [%0],[%1],4;" :: "r"(d), "l"(p));
}
__device__ __forceinline__ void cp_commit() {
    asm volatile("cp.async.commit_group;");
}
__device__ __forceinline__ void ldsm4(uint32_t* r, uint32_t a) {
    asm volatile("ldmatrix.sync.aligned.m8n8.x4.shared.b16 {%0,%1,%2,%3},[%4];"
                 : "=r"(r[0]), "=r"(r[1]), "=r"(r[2]), "=r"(r[3]) : "r"(a));
}
__device__ __forceinline__ void mma16816h(float* c, const uint32_t* a, const uint32_t* b) {
    asm volatile("mma.sync.aligned.m16n8k16.row.col.f32.f16.f16.f32 "
                 "{%0,%1,%2,%3},{%4,%5,%6,%7},{%8,%9},{%0,%1,%2,%3};"
                 : "+f"(c[0]), "+f"(c[1]), "+f"(c[2]), "+f"(c[3])
                 : "r"(a[0]), "r"(a[1]), "r"(a[2]), "r"(a[3]), "r"(b[0]), "r"(b[1]));
}

// ---------------- RMSNorm (emits fp32 h + single fp16 hf) ------------------
__global__ __launch_bounds__(256) void rmsnorm_kernel(
    const float* __restrict__ x, const float* __restrict__ w, float* __restrict__ h,
    __half* __restrict__ hf)
{
    int row = blockIdx.x;
    int tid = threadIdx.x;
    const float4* xr = (const float4*)(x + (size_t)row * HID_);
    float4 xv = xr[tid];
    float ss = xv.x * xv.x + xv.y * xv.y + xv.z * xv.z + xv.w * xv.w;
    #pragma unroll
    for (int off = 16; off; off >>= 1) ss += __shfl_xor_sync(0xFFFFFFFFu, ss, off);
    __shared__ float red[8];
    __shared__ float rtot;
    int lane = tid & 31, warp = tid >> 5;
    if (lane == 0) red[warp] = ss;
    __syncthreads();
    if (tid == 0) {
        float s = 0.f;
        #pragma unroll
        for (int i = 0; i < 8; i++) s += red[i];
        rtot = rsqrtf(s * (1.0f / HID_) + 1e-6f);
    }
    __syncthreads();
    float r = rtot;
    const float4* wr = (const float4*)w;
    float4 wv = wr[tid];
    float o[4];
    o[0] = xv.x * r * wv.x; o[1] = xv.y * r * wv.y;
    o[2] = xv.z * r * wv.z; o[3] = xv.w * r * wv.w;
    ((float4*)(h + (size_t)row * HID_))[tid] = *(float4*)o;
    size_t base = (size_t)row * HID_;
    ((__half2*)(hf + base))[tid * 2]     = __halves2half2(__float2half(o[0]), __float2half(o[1]));
    ((__half2*)(hf + base))[tid * 2 + 1] = __halves2half2(__float2half(o[2]), __float2half(o[3]));
}

// ---------------- fp32 -> fp16 hi/lo split (weights) -----------------------
__global__ __launch_bounds__(256) void splitf_kernel(
    const float* __restrict__ s, __half* __restrict__ hi,
    __half* __restrict__ lo, int n4)
{
    int i = blockIdx.x * blockDim.x + threadIdx.x;
    if (i >= n4) return;
    float4 x = ((const float4*)s)[i];
    float v[4] = {x.x, x.y, x.z, x.w};
    __half h[4], l[4];
    #pragma unroll
    for (int j = 0; j < 4; j++) {
        h[j] = __float2half(v[j]);
        l[j] = __float2half(v[j] - __half2float(h[j]));
    }
    ((__half2*)hi)[i * 2]     = __halves2half2(h[0], h[1]);
    ((__half2*)hi)[i * 2 + 1] = __halves2half2(h[2], h[3]);
    ((__half2*)lo)[i * 2]     = __halves2half2(l[0], l[1]);
    ((__half2*)lo)[i * 2 + 1] = __halves2half2(l[2], l[3]);
}

// ---------------- fp16 2-product GEMM: C = A * W^T (+bias), fp32 out ------
#define GTILE 5120               // 128 * 40 halves per tile
#define GSTAGEB (3 * GTILE * 2)  // bytes per stage (A, Bh, Bl) = 30720
#define GNST 3
#define GSMEM (GNST * GSTAGEB)   // 92160

__global__ __launch_bounds__(256, 2) void gemm_h2(
    const __half* __restrict__ A, const __half* __restrict__ Bh,
    const __half* __restrict__ Bl,
    const float* __restrict__ bias, float* __restrict__ C,
    int M, int N, int K)
{
    extern __shared__ __half sm[];
    uint32_t sbase = s2u(sm);
    int tid = threadIdx.x;
    int bm = blockIdx.y, bn = blockIdx.x;
    int w = tid >> 5, lane = tid & 31;
    int wm = (w & 3) * 32, wn = (w >> 2) * 64;
    int g = lane >> 2, tq = lane & 3;

    const __half* srcs[3];
    srcs[0] = A  + (size_t)(bm * 128) * K;
    srcs[1] = Bh + (size_t)(bn * 128) * K;
    srcs[2] = Bl + (size_t)(bn * 128) * K;

    float acc[2][8][4];
    #pragma unroll
    for (int i = 0; i < 2; i++)
        #pragma unroll
        for (int j = 0; j < 8; j++)
            #pragma unroll
            for (int q = 0; q < 4; q++) acc[i][j][q] = 0.f;

    int rA = (lane & 7) + ((lane & 8) ? 8 : 0);
    int cA = (lane & 16) ? 8 : 0;
    int rB = (lane & 7) + ((lane & 16) ? 8 : 0);
    int cB = (lane & 8) ? 8 : 0;

    auto loadStage = [&](int st, int k0) {
        #pragma unroll
        for (int mtx = 0; mtx < 3; mtx++) {
            uint32_t dbase = sbase + st * GSTAGEB + mtx * (GTILE * 2);
            const __half* s = srcs[mtx] + k0;
            #pragma unroll
            for (int rep = 0; rep < 2; rep++) {
                int j = tid + rep * 256;
                int row = j >> 2, cc = j & 3;
                cp16(dbase + row * 80 + cc * 16, s + (size_t)row * K + cc * 8);
            }
        }
    };

    loadStage(0, 0);  cp_commit();
    loadStage(1, 32); cp_commit();

    int niter = K / 32;
    for (int it = 0; it < niter; it++) {
        if (it == niter - 1) asm volatile("cp.async.wait_group 0;");
        else                 asm volatile("cp.async.wait_group 1;");
        __syncthreads();
        int cur = it % GNST;
        uint32_t stb = sbase + cur * GSTAGEB;
        #pragma unroll
        for (int ks = 0; ks < 2; ks++) {
            int kb = ks * 16;
            uint32_t a_f[2][4];
            #pragma unroll
            for (int mi = 0; mi < 2; mi++) {
                uint32_t ad = stb + ((wm + mi * 16 + rA) * 40 + kb + cA) * 2;
                ldsm4(a_f[mi], ad);
            }
            #pragma unroll
            for (int np = 0; np < 4; np++) {
                uint32_t bd = stb + GTILE * 2 + ((wn + np * 16 + rB) * 40 + kb + cB) * 2;
                uint32_t b_h[4], b_l[4];
                ldsm4(b_h, bd);
                ldsm4(b_l, bd + GTILE * 2);
                #pragma unroll
                for (int mi = 0; mi < 2; mi++) {
                    mma16816h(acc[mi][np * 2],     a_f[mi], b_h);
                    mma16816h(acc[mi][np * 2 + 1], a_f[mi], b_h + 2);
                    mma16816h(acc[mi][np * 2],     a_f[mi], b_l);
                    mma16816h(acc[mi][np * 2 + 1], a_f[mi], b_l + 2);
                }
            }
        }
        if (it + 2 < niter) { loadStage((it + 2) % GNST, (it + 2) * 32); cp_commit(); }
    }

    int rowb = bm * 128 + wm;
    int colb = bn * 128 + wn;
    #pragma unroll
    for (int mi = 0; mi < 2; mi++) {
        int r0 = rowb + mi * 16 + g;
        #pragma unroll
        for (int nj = 0; nj < 8; nj++) {
            int cc = colb + nj * 8 + tq * 2;
            float bx = 0.f, by = 0.f;
            if (bias) { float2 b2 = *(const float2*)(bias + cc); bx = b2.x; by = b2.y; }
            float2 o0, o1;
            o0.x = acc[mi][nj][0] + bx; o0.y = acc[mi][nj][1] + by;
            o1.x = acc[mi][nj][2] + bx; o1.y = acc[mi][nj][3] + by;
            *(float2*)(C + (size_t)r0 * N + cc) = o0;
            *(float2*)(C + (size_t)(r0 + 8) * N + cc) = o1;
        }
    }
}

// ---------------- Gates as tiled mini-GEMM: 128 rows x 24 outputs ----------
__global__ __launch_bounds__(128) void gates2_kernel(
    const float* __restrict__ h,
    const float* __restrict__ Wb, const float* __restrict__ bb,
    const float* __restrict__ Wi, const float* __restrict__ bi,
    const float* __restrict__ Wo, const float* __restrict__ bo,
    float* __restrict__ gates)
{
    __shared__ float hs[128 * 65];
    __shared__ float ws[24 * 64];
    int tid = threadIdx.x;
    int r0 = blockIdx.x * 128;

    float acc[24];
    #pragma unroll
    for (int c = 0; c < 24; c++) acc[c] = 0.f;

    for (int k0 = 0; k0 < HID_; k0 += 64) {
        #pragma unroll
        for (int i = 0; i < 16; i++) {
            int idx = tid + i * 128;
            int row = idx >> 4, c4 = idx & 15;
            float4 v = *(const float4*)(h + (size_t)(r0 + row) * HID_ + k0 + c4 * 4);
            float* d = &hs[row * 65 + c4 * 4];
            d[0] = v.x; d[1] = v.y; d[2] = v.z; d[3] = v.w;
        }
        #pragma unroll
        for (int i = 0; i < 3; i++) {
            int idx = tid + i * 128;
            int c = idx >> 4, j4 = idx & 15;
            const float* src = (c < 8 ? Wb + c * HID_
                               : c < 16 ? Wi + (c - 8) * HID_
                                        : Wo + (c - 16) * HID_);
            float4 v = *(const float4*)(src + k0 + j4 * 4);
            float* d = &ws[c * 64 + j4 * 4];
            d[0] = v.x; d[1] = v.y; d[2] = v.z; d[3] = v.w;
        }
        __syncthreads();
        #pragma unroll 4
        for (int j = 0; j < 64; j++) {
            float hj = hs[tid * 65 + j];
            #pragma unroll
            for (int c = 0; c < 24; c++) acc[c] += hj * ws[c * 64 + j];
        }
        __syncthreads();
    }

    int row = r0 + tid;
    int b = row >> 12, t = row & 4095;
    #pragma unroll
    for (int gt = 0; gt < 3; gt++) {
        const float* bias = (gt == 0 ? bb : gt == 1 ? bi : bo);
        #pragma unroll
        for (int hd = 0; hd < 8; hd++) {
            float val = 1.f / (1.f + expf(-(acc[gt * 8 + hd] + bias[hd])));
            gates[(size_t)gt * (B_ * NH_ * L_) + (size_t)(b * NH_ + hd) * L_ + t] = val;
        }
    }
}

// ---------------- RoPE tables ---------------------------------------------
__global__ void rope_table_kernel(float* __restrict__ tab)
{
    int idx = blockIdx.x * blockDim.x + threadIdx.x;
    if (idx >= L_ * HALF_) return;
    int t = idx >> 6, j = idx & 63;
    double invf = exp(-(double)j / 64.0 * 9.210340371976182736);
    float ang = (float)t * (float)invf;
    tab[idx] = (float)cos((double)ang);
    tab[L_ * HALF_ + idx] = (float)sin((double)ang);
}

// ---------------- RoPE apply ----------------------------------------------
__global__ __launch_bounds__(512) void rope_apply_kernel(
    float* __restrict__ q, float* __restrict__ k, const float* __restrict__ tab)
{
    int row = blockIdx.x;
    int t = row % L_;
    int tid = threadIdx.x;
    int hh = tid >> 6, j = tid & 63;
    size_t base = (size_t)row * HID_ + hh * DH_;
    float c = tab[t * HALF_ + j];
    float s = tab[L_ * HALF_ + t * HALF_ + j];
    float q1 = q[base + j], q2 = q[base + HALF_ + j];
    q[base + j]          = q1 * c - q2 * s;
    q[base + HALF_ + j]  = q1 * s + q2 * c;
    float k1 = k[base + j], k2 = k[base + HALF_ + j];
    k[base + j]          = k1 * c - k2 * s;
    k[base + HALF_ + j]  = k1 * s + k2 * c;
}

// ---------------- Recurrence: scalar fp32 math, 6-group ring ---------------
// thread (c, rg): owns M[rg*16 .. rg*16+15][col0+c]; 128 threads = 16c x 8rg.
// Plain float FFMA only (no packed f32x2 — suspected non-a-target emulation).
#define RNG 6
#define STGF 340       // floats per stage: q 8x20, k 8x20, v 16, fgo 4
#define NGRP (L_ / 8)  // 512
#define RSMEM (RNG * 8 * STGF * 4)   // 65280 bytes dynamic

__global__ __launch_bounds__(128) void recurrence5_kernel(
    const float* __restrict__ q, const float* __restrict__ k,
    const float* __restrict__ v, const float* __restrict__ gates,
    __half* __restrict__ yf)
{
    extern __shared__ float rs[];
    __shared__ __align__(16) float pp[16 * 128];
    __shared__ float ow[16];
    int split = blockIdx.x, bh = blockIdx.y;
    int b = bh >> 3, hh = bh & 7;
    int tid = threadIdx.x;
    int c = tid >> 3, rg = tid & 7;
    int col0 = split * 16;
    size_t headbase = (size_t)b * L_ * HID_ + hh * DH_;
    const float* fp = gates + (size_t)bh * L_;
    const float* gp = fp + (size_t)(B_ * NH_) * L_;
    const float* op = gp + (size_t)(B_ * NH_) * L_;
    uint32_t sb = s2u(rs);

    auto issue = [&](int t, int st) {
        uint32_t base = sb + st * (STGF * 4);
        size_t row = headbase + (size_t)t * HID_;
        if (tid < 32) {
            cp16(base + (tid >> 2) * 80 + (tid & 3) * 16, q + row + tid * 4);
        } else if (tid < 64) {
            int j = tid - 32;
            cp16(base + 640 + (j >> 2) * 80 + (j & 3) * 16, k + row + j * 4);
        } else if (tid < 68) {
            int j = tid - 64;
            cp16(base + 1280 + j * 16, v + row + col0 + j * 4);
        } else if (tid < 71) {
            int j = tid - 68;
            const float* p = (j == 0 ? fp : (j == 1 ? gp : op)) + t;
            cp4(base + 1344 + j * 4, p);
        }
    };
    auto issueGroup = [&](int g) {
        if (g < NGRP) {
            int ring = (g % RNG) * 8;
            #pragma unroll
            for (int s = 0; s < 8; s++) issue(g * 8 + s, ring + s);
        }
        cp_commit();
    };

    #pragma unroll
    for (int g = 0; g < RNG; g++) issueGroup(g);

    float M[16];
    #pragma unroll
    for (int i = 0; i < 16; i++) M[i] = 0.f;

    for (int g = 0; g < NGRP; g++) {
        asm volatile("cp.async.wait_group 5;");
        __syncthreads();                    // group g data visible to all
        int ring = (g % RNG) * 8;
        #pragma unroll
        for (int s = 0; s < 8; s++) {
            int t = g * 8 + s;
            const float* sp = rs + (ring + s) * STGF;
            float ff = sp[336];
            float gg = sp[337];
            float vv = sp[320 + c];
            if (tid == 0) ow[t & 15] = sp[338];
            float c1 = gg * SCALE_ * vv;
            const float* qp = sp + rg * 20;
            const float* kp = qp + 160;
            float p0 = 0.f, p1 = 0.f, p2 = 0.f, p3 = 0.f;
            #pragma unroll
            for (int i = 0; i < 4; i++) {
                float4 kk = *(const float4*)(kp + i * 4);
                float4 qq = *(const float4*)(qp + i * 4);
                M[i * 4 + 0] = ff * M[i * 4 + 0] + c1 * kk.x; p0 += qq.x * M[i * 4 + 0];
                M[i * 4 + 1] = ff * M[i * 4 + 1] + c1 * kk.y; p1 += qq.y * M[i * 4 + 1];
                M[i * 4 + 2] = ff * M[i * 4 + 2] + c1 * kk.z; p2 += qq.z * M[i * 4 + 2];
                M[i * 4 + 3] = ff * M[i * 4 + 3] + c1 * kk.w; p3 += qq.w * M[i * 4 + 3];
            }
            pp[(t & 15) * 128 + c * 8 + rg] = (p0 + p1) + (p2 + p3);
        }
        __syncthreads();                    // done reading ring slot + pp complete
        issueGroup(g + RNG);                // overwrite-safe now
        if (g & 1) {
            int t0i = (g - 1) * 8;
            #pragma unroll
            for (int r2 = 0; r2 < 2; r2++) {
                int oidx = tid + r2 * 128;
                int tt = oidx >> 4, ci = oidx & 15;
                float4 va = *(float4*)&pp[tt * 128 + ci * 8];
                float4 vb = *(float4*)&pp[tt * 128 + ci * 8 + 4];
                float s = ((va.x + va.y) + (va.z + va.w)) + ((vb.x + vb.y) + (vb.z + vb.w));
                float yv = ow[tt] * s;
                size_t yi = headbase + (size_t)(t0i + tt) * HID_ + col0 + ci;
                yf[yi] = __float2half(yv);
            }
        }
    }
}

// ---------------- launch ---------------------------------------------------
extern "C" void kernel_launch(void* const* d_in, const int* in_sizes, int n_in,
                              void* d_out, int out_size)
{
    const float* x      = (const float*)d_in[0];
    const float* norm_w = (const float*)d_in[1];
    const float* Wq     = (const float*)d_in[2];
    const float* Wk     = (const float*)d_in[3];
    const float* Wv     = (const float*)d_in[4];
    const float* Wbeta  = (const float*)d_in[5];
    const float* bbeta  = (const float*)d_in[6];
    const float* Wig    = (const float*)d_in[7];
    const float* big    = (const float*)d_in[8];
    const float* Wog    = (const float*)d_in[9];
    const float* bog    = (const float*)d_in[10];
    const float* Wout   = (const float*)d_in[11];
    const float* bout   = (const float*)d_in[12];
    float* out = (float*)d_out;

    float *hbuf, *qb, *kb, *vb, *gb, *rt;
    __half *hf, *yf, *wh, *wl;
    cudaGetSymbolAddress((void**)&hbuf, g_h);
    cudaGetSymbolAddress((void**)&hf,   g_hf);
    cudaGetSymbolAddress((void**)&qb,   g_q);
    cudaGetSymbolAddress((void**)&kb,   g_k);
    cudaGetSymbolAddress((void**)&vb,   g_v);
    cudaGetSymbolAddress((void**)&yf,   g_yf);
    cudaGetSymbolAddress((void**)&wh,   g_wh);
    cudaGetSymbolAddress((void**)&wl,   g_wl);
    cudaGetSymbolAddress((void**)&gb,   g_gates);
    cudaGetSymbolAddress((void**)&rt,   g_rope);

    cudaFuncSetAttribute(gemm_h2, cudaFuncAttributeMaxDynamicSharedMemorySize, GSMEM);
    cudaFuncSetAttribute(recurrence5_kernel, cudaFuncAttributeMaxDynamicSharedMemorySize, RSMEM);

    const size_t WSZ = (size_t)HID_ * HID_;
    const int n4 = (int)(WSZ / 4);
    dim3 ggrid(HID_ / 128, ROWS_ / 128);

    rmsnorm_kernel<<<ROWS_, 256>>>(x, norm_w, hbuf, hf);                            // 0
    splitf_kernel<<<(n4 + 255) / 256, 256>>>(Wq,   wh,           wl,           n4); // 1
    splitf_kernel<<<(n4 + 255) / 256, 256>>>(Wk,   wh + WSZ,     wl + WSZ,     n4); // 2
    gemm_h2<<<ggrid, 256, GSMEM>>>(hf, wh, wl, nullptr, qb, ROWS_, HID_, HID_);     // 3 (profiled)
    splitf_kernel<<<(n4 + 255) / 256, 256>>>(Wv,   wh + 2 * WSZ, wl + 2 * WSZ, n4); // 4
    gemm_h2<<<ggrid, 256, GSMEM>>>(hf, wh + WSZ,     wl + WSZ,     nullptr, kb, ROWS_, HID_, HID_);
    gemm_h2<<<ggrid, 256, GSMEM>>>(hf, wh + 2 * WSZ, wl + 2 * WSZ, nullptr, vb, ROWS_, HID_, HID_);

    splitf_kernel<<<(n4 + 255) / 256, 256>>>(Wout, wh + 3 * WSZ, wl + 3 * WSZ, n4);

    gates2_kernel<<<ROWS_ / 128, 128>>>(hbuf, Wbeta, bbeta, Wig, big, Wog, bog, gb);

    rope_table_kernel<<<(L_ * HALF_ + 255) / 256, 256>>>(rt);
    rope_apply_kernel<<<ROWS_, 512>>>(qb, kb, rt);

    recurrence5_kernel<<<dim3(8, B_ * NH_), 128, RSMEM>>>(qb, kb, vb, gb, yf);

    gemm_h2<<<ggrid, 256, GSMEM>>>(yf, wh + 3 * WSZ, wl + 3 * WSZ, bout, out, ROWS_, HID_, HID_);
}